// round 1
// baseline (speedup 1.0000x reference)
#include <cuda_runtime.h>
#include <cstdint>
#include <cstddef>

// MHA forward: B=2, S=2048, D_MODEL=1024, H=16, DK=64
// Outputs: out [2,2048,1024] then attn [2,16,2048,2048] (fp32, concatenated).

#define NEGV (-1e10f)
#define QK_SCALE 0.125f  // 1/sqrt(64)

// ---------------- device scratch (no allocations allowed) ----------------
__device__ float g_q[2 * 16 * 2048 * 64];     // [b,h,s,d]
__device__ float g_k[2 * 16 * 2048 * 64];
__device__ float g_v[2 * 16 * 2048 * 64];
__device__ float g_ctx[4096 * 1024];          // [b*s, h*64+d]
__device__ unsigned char g_mask[4096];        // canonical key_padding_mask
__device__ float g_attn[134217728];           // fallback if d_out lacks attn region

// ---------------- mask dtype detection + canonicalization ----------------
// key_padding_mask may arrive as bool(1B), int32 or float32. Inspect the first
// 4096 bytes (valid for every hypothesis) and canonicalize to uint8.
__global__ void k_mask(const unsigned int* __restrict__ raw)
{
    __shared__ int flags[4];   // notint01, anyint1, notfloat01, anyfloat1
    __shared__ int mode;
    const int tid = threadIdx.x;
    if (tid < 4) flags[tid] = 0;
    __syncthreads();
    unsigned int w = raw[tid];                       // 1024 words = 4096 bytes
    if (w > 1u) flags[0] = 1;
    if (w == 1u) flags[1] = 1;
    if (w != 0u && w != 0x3F800000u) flags[2] = 1;
    if (w == 0x3F800000u) flags[3] = 1;
    __syncthreads();
    if (tid == 0) {
        if (!flags[0] && flags[1])      mode = 0;    // int32 0/1
        else if (!flags[2] && flags[3]) mode = 1;    // float32 0/1
        else                            mode = 2;    // raw bytes (bool)
    }
    __syncthreads();
    const int md = mode;
    for (int i = tid; i < 4096; i += 1024) {
        unsigned char v;
        if (md == 0)      v = (unsigned char)(((const int*)raw)[i] != 0);
        else if (md == 1) v = (unsigned char)(((const float*)raw)[i] != 0.0f);
        else              v = (unsigned char)(((const unsigned char*)raw)[i] != 0);
        g_mask[i] = v;
    }
}

// ---------------- projection GEMM: C[m,n] = A[m,:] . W[n,:] + bias[n] -----
// M=4096, N=1024, K=1024. 128x128 tile, BK=8, 256 threads, 8x8 per thread.
// mode 0/1/2 -> scatter into g_q/g_k/g_v as [b,h,s,d]; mode 3 -> plain to out
// (A is ignored in mode 3; g_ctx is used instead).
__global__ __launch_bounds__(256) void k_gemm(
    const float* __restrict__ A, const float* __restrict__ W,
    const float* __restrict__ bias, float* __restrict__ out, int mode)
{
    __shared__ float As[8][128];
    __shared__ float Bs[8][128];
    const int tid = threadIdx.x;
    const int bm = blockIdx.y * 128;
    const int bn = blockIdx.x * 128;
    const float* Asrc = (mode == 3) ? g_ctx : A;
    float* tgt = (mode == 0) ? g_q : (mode == 1) ? g_k : (mode == 2) ? g_v : out;

    const int lr = tid >> 1;            // 0..127 (tile row to load)
    const int lc = (tid & 1) << 2;      // 0 or 4 (k-offset to load)
    const float* Ap = Asrc + (size_t)(bm + lr) * 1024 + lc;
    const float* Wp = W    + (size_t)(bn + lr) * 1024 + lc;
    const int tm0 = (tid >> 4) << 3;
    const int tn0 = (tid & 15) << 3;

    float acc[8][8];
#pragma unroll
    for (int i = 0; i < 8; i++)
#pragma unroll
        for (int j = 0; j < 8; j++) acc[i][j] = 0.0f;

    for (int k0 = 0; k0 < 1024; k0 += 8) {
        float4 a4 = *(const float4*)(Ap + k0);
        float4 w4 = *(const float4*)(Wp + k0);
        As[lc + 0][lr] = a4.x; As[lc + 1][lr] = a4.y;
        As[lc + 2][lr] = a4.z; As[lc + 3][lr] = a4.w;
        Bs[lc + 0][lr] = w4.x; Bs[lc + 1][lr] = w4.y;
        Bs[lc + 2][lr] = w4.z; Bs[lc + 3][lr] = w4.w;
        __syncthreads();
#pragma unroll
        for (int kk = 0; kk < 8; kk++) {
            float4 a0 = *(const float4*)&As[kk][tm0];
            float4 a1 = *(const float4*)&As[kk][tm0 + 4];
            float4 b0 = *(const float4*)&Bs[kk][tn0];
            float4 b1 = *(const float4*)&Bs[kk][tn0 + 4];
            float ra[8] = {a0.x, a0.y, a0.z, a0.w, a1.x, a1.y, a1.z, a1.w};
            float rb[8] = {b0.x, b0.y, b0.z, b0.w, b1.x, b1.y, b1.z, b1.w};
#pragma unroll
            for (int i = 0; i < 8; i++)
#pragma unroll
                for (int j = 0; j < 8; j++)
                    acc[i][j] = fmaf(ra[i], rb[j], acc[i][j]);
        }
        __syncthreads();
    }

#pragma unroll
    for (int i = 0; i < 8; i++) {
        const int m = bm + tm0 + i;
#pragma unroll
        for (int j = 0; j < 8; j++) {
            const int n = bn + tn0 + j;
            const float val = acc[i][j] + bias[n];
            if (mode < 3) {
                const int b = m >> 11, s = m & 2047, h = n >> 6, d = n & 63;
                tgt[(((size_t)((b << 4) + h)) * 2048 + s) * 64 + d] = val;
            } else {
                tgt[(size_t)m * 1024 + n] = val;
            }
        }
    }
}

// ---------------- scores: S[b,h,q,k] = scale*Q.K^T with exact mask set ----
// Per (b,h): 2048x2048, K-dim 64. 128x128 tile, BK=32, 8x8 per thread.
__global__ __launch_bounds__(256) void k_scores(float* __restrict__ dattn, int use_dout)
{
    __shared__ float Qs[32][128];
    __shared__ float Ks[32][128];
    float* attn = use_dout ? dattn : g_attn;
    const int tid = threadIdx.x;
    const int bh = blockIdx.z;
    const int bb = bh >> 4;
    const int q0 = blockIdx.y * 128;
    const int kb0 = blockIdx.x * 128;
    const float* Qp = g_q + (size_t)bh * 2048 * 64;
    const float* Kp = g_k + (size_t)bh * 2048 * 64;
    const int lr = tid >> 1;
    const int lcb = (tid & 1) << 4;     // 0 or 16
    const int tm0 = (tid >> 4) << 3;
    const int tn0 = (tid & 15) << 3;

    float acc[8][8];
#pragma unroll
    for (int i = 0; i < 8; i++)
#pragma unroll
        for (int j = 0; j < 8; j++) acc[i][j] = 0.0f;

    for (int c0 = 0; c0 < 64; c0 += 32) {
#pragma unroll
        for (int u = 0; u < 4; u++) {
            const int cc = lcb + u * 4;
            float4 qv = *(const float4*)(Qp + (size_t)(q0 + lr) * 64 + c0 + cc);
            float4 kv = *(const float4*)(Kp + (size_t)(kb0 + lr) * 64 + c0 + cc);
            Qs[cc + 0][lr] = qv.x; Qs[cc + 1][lr] = qv.y;
            Qs[cc + 2][lr] = qv.z; Qs[cc + 3][lr] = qv.w;
            Ks[cc + 0][lr] = kv.x; Ks[cc + 1][lr] = kv.y;
            Ks[cc + 2][lr] = kv.z; Ks[cc + 3][lr] = kv.w;
        }
        __syncthreads();
#pragma unroll
        for (int kk = 0; kk < 32; kk++) {
            float4 a0 = *(const float4*)&Qs[kk][tm0];
            float4 a1 = *(const float4*)&Qs[kk][tm0 + 4];
            float4 b0 = *(const float4*)&Ks[kk][tn0];
            float4 b1 = *(const float4*)&Ks[kk][tn0 + 4];
            float ra[8] = {a0.x, a0.y, a0.z, a0.w, a1.x, a1.y, a1.z, a1.w};
            float rb[8] = {b0.x, b0.y, b0.z, b0.w, b1.x, b1.y, b1.z, b1.w};
#pragma unroll
            for (int i = 0; i < 8; i++)
#pragma unroll
                for (int j = 0; j < 8; j++)
                    acc[i][j] = fmaf(ra[i], rb[j], acc[i][j]);
        }
        __syncthreads();
    }

    unsigned char mk[8];
#pragma unroll
    for (int j = 0; j < 8; j++) mk[j] = g_mask[bb * 2048 + kb0 + tn0 + j];

#pragma unroll
    for (int i = 0; i < 8; i++) {
        const int q = q0 + tm0 + i;
#pragma unroll
        for (int j = 0; j < 8; j++) {
            const int kx = kb0 + tn0 + j;
            float s = acc[i][j] * QK_SCALE;
            if (!mk[j]) s = NEGV;   // SET (not add): exact -1e10, matches jnp.where
            if (kx > q) s = NEGV;   // causal
            attn[((size_t)bh * 2048 + q) * 2048 + kx] = s;
        }
    }
}

// ---------------- row softmax over 2048, in place ----------------
__global__ __launch_bounds__(256) void k_softmax(float* __restrict__ dattn, int use_dout)
{
    __shared__ float red[256];
    float* attn = use_dout ? dattn : g_attn;
    float* p = attn + (size_t)blockIdx.x * 2048;
    const int tid = threadIdx.x;

    float4 v0 = *(const float4*)(p + tid * 8);
    float4 v1 = *(const float4*)(p + tid * 8 + 4);
    float lm = fmaxf(fmaxf(fmaxf(v0.x, v0.y), fmaxf(v0.z, v0.w)),
                     fmaxf(fmaxf(v1.x, v1.y), fmaxf(v1.z, v1.w)));
    red[tid] = lm;
    __syncthreads();
#pragma unroll
    for (int s = 128; s > 0; s >>= 1) {
        if (tid < s) red[tid] = fmaxf(red[tid], red[tid + s]);
        __syncthreads();
    }
    const float m = red[0];
    __syncthreads();

    float e[8];
    e[0] = expf(v0.x - m); e[1] = expf(v0.y - m);
    e[2] = expf(v0.z - m); e[3] = expf(v0.w - m);
    e[4] = expf(v1.x - m); e[5] = expf(v1.y - m);
    e[6] = expf(v1.z - m); e[7] = expf(v1.w - m);
    float ls = 0.0f;
#pragma unroll
    for (int i = 0; i < 8; i++) ls += e[i];
    red[tid] = ls;
    __syncthreads();
#pragma unroll
    for (int s = 128; s > 0; s >>= 1) {
        if (tid < s) red[tid] += red[tid + s];
        __syncthreads();
    }
    const float inv = 1.0f / red[0];

    float4 o0 = make_float4(e[0] * inv, e[1] * inv, e[2] * inv, e[3] * inv);
    float4 o1 = make_float4(e[4] * inv, e[5] * inv, e[6] * inv, e[7] * inv);
    *(float4*)(p + tid * 8) = o0;
    *(float4*)(p + tid * 8 + 4) = o1;
}

// ---------------- P @ V -> ctx[b, q, h*64+d] ----------------
// Per (b,h): M=2048 (q), N=64 (d), K=2048. 128x64 tile, BK=16, 8x4/thread.
__global__ __launch_bounds__(256) void k_pv(const float* __restrict__ dattn, int use_dout)
{
    __shared__ float As[16][128];
    __shared__ float Vs[16][64];
    const float* attn = use_dout ? dattn : g_attn;
    const int tid = threadIdx.x;
    const int bh = blockIdx.y;
    const int bb = bh >> 4, hh = bh & 15;
    const int q0 = blockIdx.x * 128;
    const float* Vp = g_v + (size_t)bh * 2048 * 64;

    const int lr = tid >> 1;            // attn tile row
    const int lc = (tid & 1) << 3;      // 0 or 8
    const int vr = tid >> 4;            // V tile row 0..15
    const int vc = (tid & 15) << 2;     // V tile col 0..60
    const int tm0 = (tid >> 4) << 3;
    const int tn0 = (tid & 15) << 2;

    float acc[8][4];
#pragma unroll
    for (int i = 0; i < 8; i++)
#pragma unroll
        for (int j = 0; j < 4; j++) acc[i][j] = 0.0f;

    for (int k0 = 0; k0 < 2048; k0 += 16) {
#pragma unroll
        for (int u = 0; u < 2; u++) {
            const int cc = lc + u * 4;
            float4 av = *(const float4*)(attn + ((size_t)bh * 2048 + q0 + lr) * 2048 + k0 + cc);
            As[cc + 0][lr] = av.x; As[cc + 1][lr] = av.y;
            As[cc + 2][lr] = av.z; As[cc + 3][lr] = av.w;
        }
        *(float4*)&Vs[vr][vc] = *(const float4*)(Vp + (size_t)(k0 + vr) * 64 + vc);
        __syncthreads();
#pragma unroll
        for (int kk = 0; kk < 16; kk++) {
            float4 a0 = *(const float4*)&As[kk][tm0];
            float4 a1 = *(const float4*)&As[kk][tm0 + 4];
            float4 bv = *(const float4*)&Vs[kk][tn0];
            float ra[8] = {a0.x, a0.y, a0.z, a0.w, a1.x, a1.y, a1.z, a1.w};
            float rb[4] = {bv.x, bv.y, bv.z, bv.w};
#pragma unroll
            for (int i = 0; i < 8; i++)
#pragma unroll
                for (int j = 0; j < 4; j++)
                    acc[i][j] = fmaf(ra[i], rb[j], acc[i][j]);
        }
        __syncthreads();
    }

#pragma unroll
    for (int i = 0; i < 8; i++) {
        const int q = q0 + tm0 + i;
#pragma unroll
        for (int j = 0; j < 4; j++)
            g_ctx[((size_t)bb * 2048 + q) * 1024 + hh * 64 + tn0 + j] = acc[i][j];
    }
}

// ---------------- launch ----------------
extern "C" void kernel_launch(void* const* d_in, const int* in_sizes, int n_in,
                              void* d_out, int out_size)
{
    const float* q_in = (const float*)d_in[0];
    const float* k_in = (const float*)d_in[1];
    const float* v_in = (const float*)d_in[2];
    const void*  mask = d_in[3];
    const float* Wq = (const float*)d_in[4];  const float* bq = (const float*)d_in[5];
    const float* Wk = (const float*)d_in[6];  const float* bk = (const float*)d_in[7];
    const float* Wv = (const float*)d_in[8];  const float* bv = (const float*)d_in[9];
    const float* Wo = (const float*)d_in[10]; const float* bo = (const float*)d_in[11];
    float* out = (float*)d_out;

    // reference returns (out, attn): out = 4,194,304 elems, attn = 134,217,728
    const int use_dout = (out_size >= 4194304 + 134217728) ? 1 : 0;
    float* dattn = out + 4194304;

    k_mask<<<1, 1024>>>((const unsigned int*)mask);

    dim3 gg(8, 32);
    k_gemm<<<gg, 256>>>(q_in, Wq, bq, nullptr, 0);
    k_gemm<<<gg, 256>>>(k_in, Wk, bk, nullptr, 1);
    k_gemm<<<gg, 256>>>(v_in, Wv, bv, nullptr, 2);

    k_scores<<<dim3(16, 16, 32), 256>>>(dattn, use_dout);
    k_softmax<<<65536, 256>>>(dattn, use_dout);
    k_pv<<<dim3(16, 32), 256>>>(dattn, use_dout);

    k_gemm<<<gg, 256>>>(nullptr, Wo, bo, out, 3);
}

// round 2
// speedup vs baseline: 1.9637x; 1.9637x over previous
#include <cuda_runtime.h>
#include <cstdint>
#include <cstddef>

// MHA forward: B=2, S=2048, D_MODEL=1024, H=16, DK=64
// Outputs: out [2,2048,1024] then attn [2,16,2048,2048] (fp32, concatenated).
// All GEMMs on tensor cores via mma.sync.m16n8k8.tf32 (cvt.rna inputs).

#define NEGV (-1e10f)
#define QK_SCALE 0.125f

// ---------------- device scratch ----------------
__device__ float g_q[2 * 16 * 2048 * 64];
__device__ float g_k[2 * 16 * 2048 * 64];
__device__ float g_v[2 * 16 * 2048 * 64];
__device__ float g_ctx[4096 * 1024];
__device__ unsigned char g_mask[4096];
__device__ float g_attn[134217728];   // fallback if d_out lacks attn region

// ---------------- helpers ----------------
__device__ __forceinline__ float t32(float x) {
    unsigned u;
    asm("cvt.rna.tf32.f32 %0, %1;" : "=r"(u) : "f"(x));
    return __uint_as_float(u);
}

__device__ __forceinline__ void mma8(float c[4], const unsigned a[4], const unsigned b[2]) {
    asm volatile("mma.sync.aligned.m16n8k8.row.col.f32.tf32.tf32.f32 "
                 "{%0,%1,%2,%3},{%4,%5,%6,%7},{%8,%9},{%0,%1,%2,%3};"
                 : "+f"(c[0]), "+f"(c[1]), "+f"(c[2]), "+f"(c[3])
                 : "r"(a[0]), "r"(a[1]), "r"(a[2]), "r"(a[3]),
                   "r"(b[0]), "r"(b[1]));
}

// ---------------- mask dtype detection + canonicalization ----------------
__global__ void k_mask(const unsigned int* __restrict__ raw)
{
    __shared__ int flags[4];
    __shared__ int mode;
    const int tid = threadIdx.x;
    if (tid < 4) flags[tid] = 0;
    __syncthreads();
    unsigned int w = raw[tid];
    if (w > 1u) flags[0] = 1;
    if (w == 1u) flags[1] = 1;
    if (w != 0u && w != 0x3F800000u) flags[2] = 1;
    if (w == 0x3F800000u) flags[3] = 1;
    __syncthreads();
    if (tid == 0) {
        if (!flags[0] && flags[1])      mode = 0;
        else if (!flags[2] && flags[3]) mode = 1;
        else                            mode = 2;
    }
    __syncthreads();
    const int md = mode;
    for (int i = tid; i < 4096; i += 1024) {
        unsigned char v;
        if (md == 0)      v = (unsigned char)(((const int*)raw)[i] != 0);
        else if (md == 1) v = (unsigned char)(((const float*)raw)[i] != 0.0f);
        else              v = (unsigned char)(((const unsigned char*)raw)[i] != 0);
        g_mask[i] = v;
    }
}

// ============ projection / output GEMM (tensor): C = A @ W^T + bias ======
// M=4096, N=1024, K=1024. Block tile 128x128, BK=32. 8 warps = 2(m) x 4(n),
// warp tile 64x32 -> 4x4 m16n8k8 tiles.
// smem: As[128][36], Ws[128][36]  (36864 B dynamic)
extern __shared__ float smem_dyn[];

__global__ __launch_bounds__(256) void k_gemm_t(
    const float* __restrict__ A, const float* __restrict__ W,
    const float* __restrict__ bias, float* __restrict__ out, int mode)
{
    float* As = smem_dyn;              // [128][36]
    float* Ws = smem_dyn + 128 * 36;   // [128][36]
    const int tid = threadIdx.x;
    const int bm = blockIdx.y * 128;
    const int bn = blockIdx.x * 128;
    const float* Asrc = (mode == 3) ? g_ctx : A;
    float* tgt = (mode == 0) ? g_q : (mode == 1) ? g_k : (mode == 2) ? g_v : out;

    const int w = tid >> 5, lane = tid & 31;
    const int g = lane >> 2, t = lane & 3;
    const int wm = (w >> 2) * 64, wn = (w & 3) * 32;
    const int lr = tid >> 1, lk = (tid & 1) * 16;
    const float* Ap = Asrc + (size_t)(bm + lr) * 1024 + lk;
    const float* Wp = W    + (size_t)(bn + lr) * 1024 + lk;

    float acc[4][4][4];
#pragma unroll
    for (int mt = 0; mt < 4; mt++)
#pragma unroll
        for (int nt = 0; nt < 4; nt++)
#pragma unroll
            for (int i = 0; i < 4; i++) acc[mt][nt][i] = 0.0f;

    for (int k0 = 0; k0 < 1024; k0 += 32) {
#pragma unroll
        for (int u = 0; u < 4; u++) {
            float4 a4 = *(const float4*)(Ap + k0 + u * 4);
            float4 w4 = *(const float4*)(Wp + k0 + u * 4);
            float* pa = As + lr * 36 + lk + u * 4;
            float* pw = Ws + lr * 36 + lk + u * 4;
            pa[0] = t32(a4.x); pa[1] = t32(a4.y); pa[2] = t32(a4.z); pa[3] = t32(a4.w);
            pw[0] = t32(w4.x); pw[1] = t32(w4.y); pw[2] = t32(w4.z); pw[3] = t32(w4.w);
        }
        __syncthreads();
#pragma unroll
        for (int kk = 0; kk < 4; kk++) {
            unsigned af[4][4], bf[4][2];
#pragma unroll
            for (int mt = 0; mt < 4; mt++) {
                const float* p = As + (wm + mt * 16 + g) * 36 + kk * 8 + t;
                af[mt][0] = __float_as_uint(p[0]);
                af[mt][1] = __float_as_uint(p[8 * 36]);
                af[mt][2] = __float_as_uint(p[4]);
                af[mt][3] = __float_as_uint(p[8 * 36 + 4]);
            }
#pragma unroll
            for (int nt = 0; nt < 4; nt++) {
                const float* p = Ws + (wn + nt * 8 + g) * 36 + kk * 8 + t;
                bf[nt][0] = __float_as_uint(p[0]);
                bf[nt][1] = __float_as_uint(p[4]);
            }
#pragma unroll
            for (int mt = 0; mt < 4; mt++)
#pragma unroll
                for (int nt = 0; nt < 4; nt++)
                    mma8(acc[mt][nt], af[mt], bf[nt]);
        }
        __syncthreads();
    }

#pragma unroll
    for (int mt = 0; mt < 4; mt++) {
#pragma unroll
        for (int nt = 0; nt < 4; nt++) {
            const int c0 = bn + wn + nt * 8 + 2 * t;
            const float b0v = bias[c0], b1v = bias[c0 + 1];
#pragma unroll
            for (int half = 0; half < 2; half++) {
                const int m = bm + wm + mt * 16 + g + half * 8;
                const float v0 = acc[mt][nt][half * 2 + 0] + b0v;
                const float v1 = acc[mt][nt][half * 2 + 1] + b1v;
                if (mode < 3) {
                    const int b = m >> 11, s = m & 2047;
                    const int h = c0 >> 6, d = c0 & 63;
                    float* dst = tgt + (((size_t)((b << 4) + h)) * 2048 + s) * 64 + d;
                    dst[0] = v0; dst[1] = v1;
                } else {
                    float* dst = tgt + (size_t)m * 1024 + c0;
                    dst[0] = v0; dst[1] = v1;
                }
            }
        }
    }
}

// ============ scores (tensor): S = scale*Q.K^T, mask SET to -1e10 ========
// Per (b,h): 2048x2048, K=64 (single smem stage).
// smem: Qs[128][68], Ks[128][68]  (69632 B dynamic)
__global__ __launch_bounds__(256) void k_scores_t(float* __restrict__ dattn, int use_dout)
{
    float* Qs = smem_dyn;              // [128][68]
    float* Ks = smem_dyn + 128 * 68;   // [128][68]
    float* attn = use_dout ? dattn : g_attn;
    const int tid = threadIdx.x;
    const int bh = blockIdx.z;
    const int bb = bh >> 4;
    const int q0 = blockIdx.y * 128;
    const int kb0 = blockIdx.x * 128;
    const float* Qp = g_q + (size_t)bh * 2048 * 64;
    const float* Kp = g_k + (size_t)bh * 2048 * 64;

    const int w = tid >> 5, lane = tid & 31;
    const int g = lane >> 2, t = lane & 3;
    const int wm = (w >> 2) * 64, wn = (w & 3) * 32;
    const int lr = tid >> 1, lc = (tid & 1) * 32;

    {
        const float* qp = Qp + (size_t)(q0 + lr) * 64 + lc;
        const float* kp = Kp + (size_t)(kb0 + lr) * 64 + lc;
#pragma unroll
        for (int u = 0; u < 8; u++) {
            float4 qv = *(const float4*)(qp + u * 4);
            float4 kv = *(const float4*)(kp + u * 4);
            float* pq = Qs + lr * 68 + lc + u * 4;
            float* pk = Ks + lr * 68 + lc + u * 4;
            pq[0] = t32(qv.x); pq[1] = t32(qv.y); pq[2] = t32(qv.z); pq[3] = t32(qv.w);
            pk[0] = t32(kv.x); pk[1] = t32(kv.y); pk[2] = t32(kv.z); pk[3] = t32(kv.w);
        }
    }
    __syncthreads();

    float acc[4][4][4];
#pragma unroll
    for (int mt = 0; mt < 4; mt++)
#pragma unroll
        for (int nt = 0; nt < 4; nt++)
#pragma unroll
            for (int i = 0; i < 4; i++) acc[mt][nt][i] = 0.0f;

#pragma unroll
    for (int kk = 0; kk < 8; kk++) {
        unsigned af[4][4], bf[4][2];
#pragma unroll
        for (int mt = 0; mt < 4; mt++) {
            const float* p = Qs + (wm + mt * 16 + g) * 68 + kk * 8 + t;
            af[mt][0] = __float_as_uint(p[0]);
            af[mt][1] = __float_as_uint(p[8 * 68]);
            af[mt][2] = __float_as_uint(p[4]);
            af[mt][3] = __float_as_uint(p[8 * 68 + 4]);
        }
#pragma unroll
        for (int nt = 0; nt < 4; nt++) {
            const float* p = Ks + (wn + nt * 8 + g) * 68 + kk * 8 + t;
            bf[nt][0] = __float_as_uint(p[0]);
            bf[nt][1] = __float_as_uint(p[4]);
        }
#pragma unroll
        for (int mt = 0; mt < 4; mt++)
#pragma unroll
            for (int nt = 0; nt < 4; nt++)
                mma8(acc[mt][nt], af[mt], bf[nt]);
    }

#pragma unroll
    for (int mt = 0; mt < 4; mt++) {
#pragma unroll
        for (int nt = 0; nt < 4; nt++) {
            const int c0 = kb0 + wn + nt * 8 + 2 * t;
            const unsigned char mk0 = g_mask[bb * 2048 + c0];
            const unsigned char mk1 = g_mask[bb * 2048 + c0 + 1];
#pragma unroll
            for (int half = 0; half < 2; half++) {
                const int q = q0 + wm + mt * 16 + g + half * 8;
                float v0 = acc[mt][nt][half * 2 + 0] * QK_SCALE;
                float v1 = acc[mt][nt][half * 2 + 1] * QK_SCALE;
                if (!mk0 || c0 > q)     v0 = NEGV;
                if (!mk1 || c0 + 1 > q) v1 = NEGV;
                float2* dst = (float2*)(attn + ((size_t)bh * 2048 + q) * 2048 + c0);
                *dst = make_float2(v0, v1);
            }
        }
    }
}

// ---------------- row softmax over 2048, in place ----------------
__global__ __launch_bounds__(256) void k_softmax(float* __restrict__ dattn, int use_dout)
{
    __shared__ float red[256];
    float* attn = use_dout ? dattn : g_attn;
    float* p = attn + (size_t)blockIdx.x * 2048;
    const int tid = threadIdx.x;

    float4 v0 = *(const float4*)(p + tid * 8);
    float4 v1 = *(const float4*)(p + tid * 8 + 4);
    float lm = fmaxf(fmaxf(fmaxf(v0.x, v0.y), fmaxf(v0.z, v0.w)),
                     fmaxf(fmaxf(v1.x, v1.y), fmaxf(v1.z, v1.w)));
    red[tid] = lm;
    __syncthreads();
#pragma unroll
    for (int s = 128; s > 0; s >>= 1) {
        if (tid < s) red[tid] = fmaxf(red[tid], red[tid + s]);
        __syncthreads();
    }
    const float m = red[0];
    __syncthreads();

    float e[8];
    e[0] = expf(v0.x - m); e[1] = expf(v0.y - m);
    e[2] = expf(v0.z - m); e[3] = expf(v0.w - m);
    e[4] = expf(v1.x - m); e[5] = expf(v1.y - m);
    e[6] = expf(v1.z - m); e[7] = expf(v1.w - m);
    float ls = 0.0f;
#pragma unroll
    for (int i = 0; i < 8; i++) ls += e[i];
    red[tid] = ls;
    __syncthreads();
#pragma unroll
    for (int s = 128; s > 0; s >>= 1) {
        if (tid < s) red[tid] += red[tid + s];
        __syncthreads();
    }
    const float inv = 1.0f / red[0];

    *(float4*)(p + tid * 8)     = make_float4(e[0] * inv, e[1] * inv, e[2] * inv, e[3] * inv);
    *(float4*)(p + tid * 8 + 4) = make_float4(e[4] * inv, e[5] * inv, e[6] * inv, e[7] * inv);
}

// ============ P @ V (tensor) -> ctx[b, q, h*64+d] ========================
// Per (b,h): M=2048(q), N=64(d), K=2048. Block 128x64, K-chunk 128.
// 8 warps = 4(m) x 2(n), warp tile 32x32 -> 2x4 m16n8k8 tiles.
// smem: Ps[128][132], Vs[128][68]  (102400 B dynamic)
__global__ __launch_bounds__(256) void k_pv_t(const float* __restrict__ dattn, int use_dout)
{
    float* Ps = smem_dyn;               // [128][132]
    float* Vs = smem_dyn + 128 * 132;   // [128][68]
    const float* attn = use_dout ? dattn : g_attn;
    const int tid = threadIdx.x;
    const int bh = blockIdx.y;
    const int bb = bh >> 4, hh = bh & 15;
    const int q0 = blockIdx.x * 128;
    const float* Vp = g_v + (size_t)bh * 2048 * 64;

    const int w = tid >> 5, lane = tid & 31;
    const int g = lane >> 2, t = lane & 3;
    const int wm = (w >> 1) * 32, wn = (w & 1) * 32;
    const int lr = tid >> 1;
    const int lcp = (tid & 1) * 64;     // P col base (of 128)
    const int lcv = (tid & 1) * 32;     // V col base (of 64)

    float acc[2][4][4];
#pragma unroll
    for (int mt = 0; mt < 2; mt++)
#pragma unroll
        for (int nt = 0; nt < 4; nt++)
#pragma unroll
            for (int i = 0; i < 4; i++) acc[mt][nt][i] = 0.0f;

    for (int k0 = 0; k0 < 2048; k0 += 128) {
        {
            const float* pp = attn + ((size_t)bh * 2048 + q0 + lr) * 2048 + k0 + lcp;
#pragma unroll
            for (int u = 0; u < 16; u++) {
                float4 v = *(const float4*)(pp + u * 4);
                float* d = Ps + lr * 132 + lcp + u * 4;
                d[0] = t32(v.x); d[1] = t32(v.y); d[2] = t32(v.z); d[3] = t32(v.w);
            }
            const float* vp = Vp + (size_t)(k0 + lr) * 64 + lcv;
#pragma unroll
            for (int u = 0; u < 8; u++) {
                float4 v = *(const float4*)(vp + u * 4);
                float* d = Vs + lr * 68 + lcv + u * 4;
                d[0] = t32(v.x); d[1] = t32(v.y); d[2] = t32(v.z); d[3] = t32(v.w);
            }
        }
        __syncthreads();
#pragma unroll
        for (int kk = 0; kk < 16; kk++) {
            unsigned af[2][4], bf[4][2];
#pragma unroll
            for (int mt = 0; mt < 2; mt++) {
                const float* p = Ps + (wm + mt * 16 + g) * 132 + kk * 8 + t;
                af[mt][0] = __float_as_uint(p[0]);
                af[mt][1] = __float_as_uint(p[8 * 132]);
                af[mt][2] = __float_as_uint(p[4]);
                af[mt][3] = __float_as_uint(p[8 * 132 + 4]);
            }
#pragma unroll
            for (int nt = 0; nt < 4; nt++) {
                const float* p = Vs + (kk * 8 + t) * 68 + wn + nt * 8 + g;
                bf[nt][0] = __float_as_uint(p[0]);
                bf[nt][1] = __float_as_uint(p[4 * 68]);
            }
#pragma unroll
            for (int mt = 0; mt < 2; mt++)
#pragma unroll
                for (int nt = 0; nt < 4; nt++)
                    mma8(acc[mt][nt], af[mt], bf[nt]);
        }
        __syncthreads();
    }

#pragma unroll
    for (int mt = 0; mt < 2; mt++) {
#pragma unroll
        for (int nt = 0; nt < 4; nt++) {
            const int d0 = wn + nt * 8 + 2 * t;
#pragma unroll
            for (int half = 0; half < 2; half++) {
                const int q = q0 + wm + mt * 16 + g + half * 8;
                float2* dst = (float2*)(g_ctx + ((size_t)bb * 2048 + q) * 1024 + hh * 64 + d0);
                *dst = make_float2(acc[mt][nt][half * 2 + 0], acc[mt][nt][half * 2 + 1]);
            }
        }
    }
}

// ---------------- launch ----------------
extern "C" void kernel_launch(void* const* d_in, const int* in_sizes, int n_in,
                              void* d_out, int out_size)
{
    const float* q_in = (const float*)d_in[0];
    const float* k_in = (const float*)d_in[1];
    const float* v_in = (const float*)d_in[2];
    const void*  mask = d_in[3];
    const float* Wq = (const float*)d_in[4];  const float* bq = (const float*)d_in[5];
    const float* Wk = (const float*)d_in[6];  const float* bk = (const float*)d_in[7];
    const float* Wv = (const float*)d_in[8];  const float* bv = (const float*)d_in[9];
    const float* Wo = (const float*)d_in[10]; const float* bo = (const float*)d_in[11];
    float* out = (float*)d_out;

    const int use_dout = (out_size >= 4194304 + 134217728) ? 1 : 0;
    float* dattn = out + 4194304;

    const int SM_G = 2 * 128 * 36 * 4;                  // 36864
    const int SM_S = 2 * 128 * 68 * 4;                  // 69632
    const int SM_P = (128 * 132 + 128 * 68) * 4;        // 102400
    cudaFuncSetAttribute(k_scores_t, cudaFuncAttributeMaxDynamicSharedMemorySize, SM_S);
    cudaFuncSetAttribute(k_pv_t,     cudaFuncAttributeMaxDynamicSharedMemorySize, SM_P);

    k_mask<<<1, 1024>>>((const unsigned int*)mask);

    dim3 gg(8, 32);
    k_gemm_t<<<gg, 256, SM_G>>>(q_in, Wq, bq, nullptr, 0);
    k_gemm_t<<<gg, 256, SM_G>>>(k_in, Wk, bk, nullptr, 1);
    k_gemm_t<<<gg, 256, SM_G>>>(v_in, Wv, bv, nullptr, 2);

    k_scores_t<<<dim3(16, 16, 32), 256, SM_S>>>(dattn, use_dout);
    k_softmax<<<65536, 256>>>(dattn, use_dout);
    k_pv_t<<<dim3(16, 32), 256, SM_P>>>(dattn, use_dout);

    k_gemm_t<<<gg, 256, SM_G>>>(q_in, Wo, bo, out, 3);
}

// round 3
// speedup vs baseline: 2.7137x; 1.3820x over previous
#include <cuda_runtime.h>
#include <cstdint>
#include <cstddef>

// MHA forward: B=2, S=2048, D_MODEL=1024, H=16, DK=64
// Outputs: out [2,2048,1024] then attn [2,16,2048,2048] (fp32, concatenated).
// GEMMs on tensor cores (mma.sync m16n8k8 tf32). Attention core fused:
// scores + softmax + PV in one kernel, attn written exactly once.

#define NEGV (-1e10f)
#define QK_SCALE 0.125f
#define UNIF 0.00048828125f   // 1/2048, exact power of two

// ---------------- device scratch ----------------
__device__ float g_q[2 * 16 * 2048 * 64];
__device__ float g_k[2 * 16 * 2048 * 64];
__device__ float g_v[2 * 16 * 2048 * 64];
__device__ float g_ctx[4096 * 1024];
__device__ unsigned char g_mask[4096];
__device__ float g_attn[134217728];   // fallback if d_out lacks attn region

// ---------------- helpers ----------------
__device__ __forceinline__ float t32(float x) {
    unsigned u;
    asm("cvt.rna.tf32.f32 %0, %1;" : "=r"(u) : "f"(x));
    return __uint_as_float(u);
}

__device__ __forceinline__ void mma8(float c[4], const unsigned a[4], const unsigned b[2]) {
    asm volatile("mma.sync.aligned.m16n8k8.row.col.f32.tf32.tf32.f32 "
                 "{%0,%1,%2,%3},{%4,%5,%6,%7},{%8,%9},{%0,%1,%2,%3};"
                 : "+f"(c[0]), "+f"(c[1]), "+f"(c[2]), "+f"(c[3])
                 : "r"(a[0]), "r"(a[1]), "r"(a[2]), "r"(a[3]),
                   "r"(b[0]), "r"(b[1]));
}

// ---------------- mask dtype detection + canonicalization ----------------
__global__ void k_mask(const unsigned int* __restrict__ raw)
{
    __shared__ int flags[4];
    __shared__ int mode;
    const int tid = threadIdx.x;
    if (tid < 4) flags[tid] = 0;
    __syncthreads();
    unsigned int w = raw[tid];
    if (w > 1u) flags[0] = 1;
    if (w == 1u) flags[1] = 1;
    if (w != 0u && w != 0x3F800000u) flags[2] = 1;
    if (w == 0x3F800000u) flags[3] = 1;
    __syncthreads();
    if (tid == 0) {
        if (!flags[0] && flags[1])      mode = 0;
        else if (!flags[2] && flags[3]) mode = 1;
        else                            mode = 2;
    }
    __syncthreads();
    const int md = mode;
    for (int i = tid; i < 4096; i += 1024) {
        unsigned char v;
        if (md == 0)      v = (unsigned char)(((const int*)raw)[i] != 0);
        else if (md == 1) v = (unsigned char)(((const float*)raw)[i] != 0.0f);
        else              v = (unsigned char)(((const unsigned char*)raw)[i] != 0);
        g_mask[i] = v;
    }
}

// ============ projection / output GEMM (tensor): C = A @ W^T + bias ======
extern __shared__ float smem_dyn[];

__global__ __launch_bounds__(256) void k_gemm_t(
    const float* __restrict__ A, const float* __restrict__ W,
    const float* __restrict__ bias, float* __restrict__ out, int mode)
{
    float* As = smem_dyn;              // [128][36]
    float* Ws = smem_dyn + 128 * 36;   // [128][36]
    const int tid = threadIdx.x;
    const int bm = blockIdx.y * 128;
    const int bn = blockIdx.x * 128;
    const float* Asrc = (mode == 3) ? g_ctx : A;
    float* tgt = (mode == 0) ? g_q : (mode == 1) ? g_k : (mode == 2) ? g_v : out;

    const int w = tid >> 5, lane = tid & 31;
    const int g = lane >> 2, t = lane & 3;
    const int wm = (w >> 2) * 64, wn = (w & 3) * 32;
    const int lr = tid >> 1, lk = (tid & 1) * 16;
    const float* Ap = Asrc + (size_t)(bm + lr) * 1024 + lk;
    const float* Wp = W    + (size_t)(bn + lr) * 1024 + lk;

    float acc[4][4][4];
#pragma unroll
    for (int mt = 0; mt < 4; mt++)
#pragma unroll
        for (int nt = 0; nt < 4; nt++)
#pragma unroll
            for (int i = 0; i < 4; i++) acc[mt][nt][i] = 0.0f;

    for (int k0 = 0; k0 < 1024; k0 += 32) {
#pragma unroll
        for (int u = 0; u < 4; u++) {
            float4 a4 = *(const float4*)(Ap + k0 + u * 4);
            float4 w4 = *(const float4*)(Wp + k0 + u * 4);
            float* pa = As + lr * 36 + lk + u * 4;
            float* pw = Ws + lr * 36 + lk + u * 4;
            pa[0] = t32(a4.x); pa[1] = t32(a4.y); pa[2] = t32(a4.z); pa[3] = t32(a4.w);
            pw[0] = t32(w4.x); pw[1] = t32(w4.y); pw[2] = t32(w4.z); pw[3] = t32(w4.w);
        }
        __syncthreads();
#pragma unroll
        for (int kk = 0; kk < 4; kk++) {
            unsigned af[4][4], bf[4][2];
#pragma unroll
            for (int mt = 0; mt < 4; mt++) {
                const float* p = As + (wm + mt * 16 + g) * 36 + kk * 8 + t;
                af[mt][0] = __float_as_uint(p[0]);
                af[mt][1] = __float_as_uint(p[8 * 36]);
                af[mt][2] = __float_as_uint(p[4]);
                af[mt][3] = __float_as_uint(p[8 * 36 + 4]);
            }
#pragma unroll
            for (int nt = 0; nt < 4; nt++) {
                const float* p = Ws + (wn + nt * 8 + g) * 36 + kk * 8 + t;
                bf[nt][0] = __float_as_uint(p[0]);
                bf[nt][1] = __float_as_uint(p[4]);
            }
#pragma unroll
            for (int mt = 0; mt < 4; mt++)
#pragma unroll
                for (int nt = 0; nt < 4; nt++)
                    mma8(acc[mt][nt], af[mt], bf[nt]);
        }
        __syncthreads();
    }

#pragma unroll
    for (int mt = 0; mt < 4; mt++) {
#pragma unroll
        for (int nt = 0; nt < 4; nt++) {
            const int c0 = bn + wn + nt * 8 + 2 * t;
            const float b0v = bias[c0], b1v = bias[c0 + 1];
#pragma unroll
            for (int half = 0; half < 2; half++) {
                const int m = bm + wm + mt * 16 + g + half * 8;
                const float v0 = acc[mt][nt][half * 2 + 0] + b0v;
                const float v1 = acc[mt][nt][half * 2 + 1] + b1v;
                if (mode < 3) {
                    const int b = m >> 11, s = m & 2047;
                    const int h = c0 >> 6, d = c0 & 63;
                    float* dst = tgt + (((size_t)((b << 4) + h)) * 2048 + s) * 64 + d;
                    dst[0] = v0; dst[1] = v1;
                } else {
                    float* dst = tgt + (size_t)m * 1024 + c0;
                    dst[0] = v0; dst[1] = v1;
                }
            }
        }
    }
}

// ============ fused attention core ======================================
// One block per (bh, q-tile of 128). Pass A: S=QK^T -> rowsum of exp.
// Pass B: recompute S, p = exp(s)/sum (uniform fallback), write attn once,
// PV mma from smem. smem ~175KB.
// Float-region offsets (in floats):
//   Qs 0..8703 [128][68], Ks 8704.. [128][68], Vs 17408.. [128][68],
//   Ps 26112.. [128][132], rowsum 43008, rinv 43136, runi 43264(int),
//   hasuni 43392(int), mask bytes at float idx 43394 (8B aligned)
__global__ __launch_bounds__(256) void k_attn(float* __restrict__ dattn, int use_dout)
{
    float* Qs = smem_dyn;
    float* Ks = smem_dyn + 8704;
    float* Vs = smem_dyn + 17408;
    float* Ps = smem_dyn + 26112;
    float* rowsum = smem_dyn + 43008;
    float* rinv   = smem_dyn + 43136;
    int*   runi   = (int*)(smem_dyn + 43264);
    int*   hasuniS= (int*)(smem_dyn + 43392);
    unsigned char* Ms = (unsigned char*)(smem_dyn + 43394);

    float* attn = use_dout ? dattn : g_attn;
    const int tid = threadIdx.x;
    const int bh = blockIdx.y;
    const int bb = bh >> 4, hh = bh & 15;
    const int q0 = blockIdx.x * 128;
    const float* Qp = g_q + (size_t)bh * 2048 * 64;
    const float* Kp = g_k + (size_t)bh * 2048 * 64;
    const float* Vp = g_v + (size_t)bh * 2048 * 64;

    const int w = tid >> 5, lane = tid & 31;
    const int g = lane >> 2, t = lane & 3;
    const int wmS = (w >> 2) * 64, wnS = (w & 3) * 32;   // scores map 2x4
    const int wmO = (w >> 1) * 32, wnO = (w & 1) * 32;   // PV map 4x2
    const int lr = tid >> 1, lc = (tid & 1) * 32;

    // ---- init ----
    if (tid < 128) rowsum[tid] = 0.0f;
    if (tid == 0) hasuniS[0] = 0;
    ((unsigned long long*)Ms)[tid] =
        ((const unsigned long long*)(g_mask + bb * 2048))[tid];
    {
        const float* qp = Qp + (size_t)(q0 + lr) * 64 + lc;
        float* pq = Qs + lr * 68 + lc;
#pragma unroll
        for (int u = 0; u < 8; u++) {
            float4 v = *(const float4*)(qp + u * 4);
            pq[u*4+0] = t32(v.x); pq[u*4+1] = t32(v.y);
            pq[u*4+2] = t32(v.z); pq[u*4+3] = t32(v.w);
        }
    }
    __syncthreads();

    // ---- Pass A: rowsum of exp(s) over causal-live chunks ----
    float rs[4][2];
#pragma unroll
    for (int mt = 0; mt < 4; mt++) { rs[mt][0] = 0.0f; rs[mt][1] = 0.0f; }

    const int nA = blockIdx.x + 1;   // chunks 0..q-tile index are causal-live
    for (int kc = 0; kc < nA; kc++) {
        const int kc0 = kc * 128;
        if (kc) __syncthreads();
        {
            const float* kp = Kp + (size_t)(kc0 + lr) * 64 + lc;
            float* pk = Ks + lr * 68 + lc;
#pragma unroll
            for (int u = 0; u < 8; u++) {
                float4 v = *(const float4*)(kp + u * 4);
                pk[u*4+0] = t32(v.x); pk[u*4+1] = t32(v.y);
                pk[u*4+2] = t32(v.z); pk[u*4+3] = t32(v.w);
            }
        }
        __syncthreads();

        float acc[4][4][4];
#pragma unroll
        for (int mt = 0; mt < 4; mt++)
#pragma unroll
            for (int nt = 0; nt < 4; nt++)
#pragma unroll
                for (int i = 0; i < 4; i++) acc[mt][nt][i] = 0.0f;
#pragma unroll
        for (int kk = 0; kk < 8; kk++) {
            unsigned af[4][4], bf[4][2];
#pragma unroll
            for (int mt = 0; mt < 4; mt++) {
                const float* p = Qs + (wmS + mt * 16 + g) * 68 + kk * 8 + t;
                af[mt][0] = __float_as_uint(p[0]);
                af[mt][1] = __float_as_uint(p[8 * 68]);
                af[mt][2] = __float_as_uint(p[4]);
                af[mt][3] = __float_as_uint(p[8 * 68 + 4]);
            }
#pragma unroll
            for (int nt = 0; nt < 4; nt++) {
                const float* p = Ks + (wnS + nt * 8 + g) * 68 + kk * 8 + t;
                bf[nt][0] = __float_as_uint(p[0]);
                bf[nt][1] = __float_as_uint(p[4]);
            }
#pragma unroll
            for (int mt = 0; mt < 4; mt++)
#pragma unroll
                for (int nt = 0; nt < 4; nt++)
                    mma8(acc[mt][nt], af[mt], bf[nt]);
        }

#pragma unroll
        for (int nt = 0; nt < 4; nt++) {
            const int c0 = kc0 + wnS + nt * 8 + 2 * t;
            const unsigned char mk0 = Ms[c0], mk1 = Ms[c0 + 1];
#pragma unroll
            for (int mt = 0; mt < 4; mt++) {
#pragma unroll
                for (int half = 0; half < 2; half++) {
                    const int rq = q0 + wmS + mt * 16 + g + half * 8;
                    const float s0 = acc[mt][nt][half*2+0] * QK_SCALE;
                    const float s1 = acc[mt][nt][half*2+1] * QK_SCALE;
                    float e0 = (!mk0 || c0 > rq)     ? 0.0f : __expf(s0);
                    float e1 = (!mk1 || c0 + 1 > rq) ? 0.0f : __expf(s1);
                    rs[mt][half] += e0 + e1;
                }
            }
        }
    }
    // reduce rs across the 4 t-lanes of each quad, then atomic into rowsum
#pragma unroll
    for (int mt = 0; mt < 4; mt++)
#pragma unroll
        for (int half = 0; half < 2; half++) {
            float v = rs[mt][half];
            v += __shfl_xor_sync(0xffffffffu, v, 1);
            v += __shfl_xor_sync(0xffffffffu, v, 2);
            if (t == 0) atomicAdd(&rowsum[wmS + mt * 16 + g + 8 * half], v);
        }
    __syncthreads();
    if (tid < 128) {
        const float s = rowsum[tid];
        if (s == 0.0f) { runi[tid] = 1; rinv[tid] = 0.0f; hasuniS[0] = 1; }
        else           { runi[tid] = 0; rinv[tid] = 1.0f / s; }
    }
    __syncthreads();
    const int hasuni = hasuniS[0];

    // ---- Pass B: recompute, write attn once, accumulate PV ----
    float oacc[2][4][4];
#pragma unroll
    for (int mt = 0; mt < 2; mt++)
#pragma unroll
        for (int nt = 0; nt < 4; nt++)
#pragma unroll
            for (int i = 0; i < 4; i++) oacc[mt][nt][i] = 0.0f;

    for (int kc = 0; kc < 16; kc++) {
        const int kc0 = kc * 128;
        const bool maskedc = (kc0 > q0 + 127);

        if (maskedc && !hasuni) {
            // entire chunk is exactly zero in the reference
            const float4 z = make_float4(0.f, 0.f, 0.f, 0.f);
#pragma unroll
            for (int u = 0; u < 16; u++) {
                const int f = tid + 256 * u;
                const int r = f >> 5, c = (f & 31) * 4;
                *(float4*)(attn + ((size_t)(bh * 2048 + q0 + r)) * 2048 + kc0 + c) = z;
            }
            continue;
        }

        __syncthreads();   // previous chunk's Ps/Vs consumers are done
        if (!maskedc) {
            const float* kp = Kp + (size_t)(kc0 + lr) * 64 + lc;
            float* pk = Ks + lr * 68 + lc;
#pragma unroll
            for (int u = 0; u < 8; u++) {
                float4 v = *(const float4*)(kp + u * 4);
                pk[u*4+0] = t32(v.x); pk[u*4+1] = t32(v.y);
                pk[u*4+2] = t32(v.z); pk[u*4+3] = t32(v.w);
            }
        }
        {
            const float* vp = Vp + (size_t)(kc0 + lr) * 64 + lc;
            float* pv = Vs + lr * 68 + lc;
#pragma unroll
            for (int u = 0; u < 8; u++) {
                float4 v = *(const float4*)(vp + u * 4);
                pv[u*4+0] = t32(v.x); pv[u*4+1] = t32(v.y);
                pv[u*4+2] = t32(v.z); pv[u*4+3] = t32(v.w);
            }
        }
        if (maskedc) {
            // uniform rows get 1/2048, others 0
#pragma unroll
            for (int u = 0; u < 16; u++) {
                const int f = tid + 256 * u;
                const int r = f >> 5, c = (f & 31) * 4;
                const float pvv = runi[r] ? UNIF : 0.0f;
                *(float4*)(Ps + r * 132 + c) = make_float4(pvv, pvv, pvv, pvv);
            }
        }
        __syncthreads();

        if (!maskedc) {
            float acc[4][4][4];
#pragma unroll
            for (int mt = 0; mt < 4; mt++)
#pragma unroll
                for (int nt = 0; nt < 4; nt++)
#pragma unroll
                    for (int i = 0; i < 4; i++) acc[mt][nt][i] = 0.0f;
#pragma unroll
            for (int kk = 0; kk < 8; kk++) {
                unsigned af[4][4], bf[4][2];
#pragma unroll
                for (int mt = 0; mt < 4; mt++) {
                    const float* p = Qs + (wmS + mt * 16 + g) * 68 + kk * 8 + t;
                    af[mt][0] = __float_as_uint(p[0]);
                    af[mt][1] = __float_as_uint(p[8 * 68]);
                    af[mt][2] = __float_as_uint(p[4]);
                    af[mt][3] = __float_as_uint(p[8 * 68 + 4]);
                }
#pragma unroll
                for (int nt = 0; nt < 4; nt++) {
                    const float* p = Ks + (wnS + nt * 8 + g) * 68 + kk * 8 + t;
                    bf[nt][0] = __float_as_uint(p[0]);
                    bf[nt][1] = __float_as_uint(p[4]);
                }
#pragma unroll
                for (int mt = 0; mt < 4; mt++)
#pragma unroll
                    for (int nt = 0; nt < 4; nt++)
                        mma8(acc[mt][nt], af[mt], bf[nt]);
            }
#pragma unroll
            for (int mt = 0; mt < 4; mt++) {
#pragma unroll
                for (int half = 0; half < 2; half++) {
                    const int rl = wmS + mt * 16 + g + 8 * half;
                    const int rq = q0 + rl;
                    const float ri = rinv[rl];
                    const int un = runi[rl];
#pragma unroll
                    for (int nt = 0; nt < 4; nt++) {
                        const int cl = wnS + nt * 8 + 2 * t;
                        const int c0 = kc0 + cl;
                        const unsigned char mk0 = Ms[c0], mk1 = Ms[c0 + 1];
                        const float s0 = acc[mt][nt][half*2+0] * QK_SCALE;
                        const float s1 = acc[mt][nt][half*2+1] * QK_SCALE;
                        float e0 = (!mk0 || c0 > rq)     ? 0.0f : __expf(s0);
                        float e1 = (!mk1 || c0 + 1 > rq) ? 0.0f : __expf(s1);
                        float p0 = un ? UNIF : e0 * ri;
                        float p1 = un ? UNIF : e1 * ri;
                        *(float2*)(Ps + rl * 132 + cl) = make_float2(p0, p1);
                    }
                }
            }
            __syncthreads();
        }

        // write attn chunk from Ps (coalesced, fp32 exact)
#pragma unroll
        for (int u = 0; u < 16; u++) {
            const int f = tid + 256 * u;
            const int r = f >> 5, c = (f & 31) * 4;
            float4 v = *(const float4*)(Ps + r * 132 + c);
            *(float4*)(attn + ((size_t)(bh * 2048 + q0 + r)) * 2048 + kc0 + c) = v;
        }

        // PV mma: oacc += Ps(t32) @ Vs
#pragma unroll
        for (int kk = 0; kk < 16; kk++) {
            unsigned af[2][4], bf[4][2];
#pragma unroll
            for (int mt = 0; mt < 2; mt++) {
                const float* p = Ps + (wmO + mt * 16 + g) * 132 + kk * 8 + t;
                af[mt][0] = __float_as_uint(t32(p[0]));
                af[mt][1] = __float_as_uint(t32(p[8 * 132]));
                af[mt][2] = __float_as_uint(t32(p[4]));
                af[mt][3] = __float_as_uint(t32(p[8 * 132 + 4]));
            }
#pragma unroll
            for (int nt = 0; nt < 4; nt++) {
                const float* p = Vs + (kk * 8 + t) * 68 + wnO + nt * 8 + g;
                bf[nt][0] = __float_as_uint(p[0]);
                bf[nt][1] = __float_as_uint(p[4 * 68]);
            }
#pragma unroll
            for (int mt = 0; mt < 2; mt++)
#pragma unroll
                for (int nt = 0; nt < 4; nt++)
                    mma8(oacc[mt][nt], af[mt], bf[nt]);
        }
    }

    // ---- write ctx ----
#pragma unroll
    for (int mt = 0; mt < 2; mt++) {
#pragma unroll
        for (int nt = 0; nt < 4; nt++) {
            const int d0 = wnO + nt * 8 + 2 * t;
#pragma unroll
            for (int half = 0; half < 2; half++) {
                const int rq = q0 + wmO + mt * 16 + g + half * 8;
                *(float2*)(g_ctx + ((size_t)(bb * 2048 + rq)) * 1024 + hh * 64 + d0)
                    = make_float2(oacc[mt][nt][half*2+0], oacc[mt][nt][half*2+1]);
            }
        }
    }
}

// ---------------- launch ----------------
extern "C" void kernel_launch(void* const* d_in, const int* in_sizes, int n_in,
                              void* d_out, int out_size)
{
    const float* q_in = (const float*)d_in[0];
    const float* k_in = (const float*)d_in[1];
    const float* v_in = (const float*)d_in[2];
    const void*  mask = d_in[3];
    const float* Wq = (const float*)d_in[4];  const float* bq = (const float*)d_in[5];
    const float* Wk = (const float*)d_in[6];  const float* bk = (const float*)d_in[7];
    const float* Wv = (const float*)d_in[8];  const float* bv = (const float*)d_in[9];
    const float* Wo = (const float*)d_in[10]; const float* bo = (const float*)d_in[11];
    float* out = (float*)d_out;

    const int use_dout = (out_size >= 4194304 + 134217728) ? 1 : 0;
    float* dattn = out + 4194304;

    const int SM_G = 2 * 128 * 36 * 4;        // 36864
    const int SM_A = 43394 * 4 + 2048 + 32;   // ~175.7 KB
    cudaFuncSetAttribute(k_attn, cudaFuncAttributeMaxDynamicSharedMemorySize, SM_A);

    k_mask<<<1, 1024>>>((const unsigned int*)mask);

    dim3 gg(8, 32);
    k_gemm_t<<<gg, 256, SM_G>>>(q_in, Wq, bq, nullptr, 0);
    k_gemm_t<<<gg, 256, SM_G>>>(k_in, Wk, bk, nullptr, 1);
    k_gemm_t<<<gg, 256, SM_G>>>(v_in, Wv, bv, nullptr, 2);

    k_attn<<<dim3(16, 32), 256, SM_A>>>(dattn, use_dout);

    k_gemm_t<<<gg, 256, SM_G>>>(q_in, Wo, bo, out, 3);
}

// round 5
// speedup vs baseline: 3.2987x; 1.2156x over previous
#include <cuda_runtime.h>
#include <cstdint>
#include <cstddef>

// MHA forward: B=2, S=2048, D_MODEL=1024, H=16, DK=64
// Outputs: out [2,2048,1024] then attn [2,16,2048,2048] (fp32, concatenated).
// tf32 mma.sync everywhere; q/k/v pre-rounded to tf32 at projection epilogue
// so the fused attention kernel streams tiles with cp.async (no cvt on path).

#define QK_SCALE 0.125f
#define UNIF 0.00048828125f   // 1/2048, exact power of two

// ---------------- device scratch ----------------
__device__ __align__(256) float g_q[2 * 16 * 2048 * 64];
__device__ __align__(256) float g_k[2 * 16 * 2048 * 64];
__device__ __align__(256) float g_v[2 * 16 * 2048 * 64];
__device__ __align__(256) float g_ctx[4096 * 1024];
__device__ __align__(256) unsigned char g_mask[4096];
__device__ __align__(256) float g_attn[134217728];  // fallback

// ---------------- helpers ----------------
__device__ __forceinline__ float t32(float x) {
    unsigned u;
    asm("cvt.rna.tf32.f32 %0, %1;" : "=r"(u) : "f"(x));
    return __uint_as_float(u);
}

__device__ __forceinline__ void mma8(float c[4], const unsigned a[4], const unsigned b[2]) {
    asm volatile("mma.sync.aligned.m16n8k8.row.col.f32.tf32.tf32.f32 "
                 "{%0,%1,%2,%3},{%4,%5,%6,%7},{%8,%9},{%0,%1,%2,%3};"
                 : "+f"(c[0]), "+f"(c[1]), "+f"(c[2]), "+f"(c[3])
                 : "r"(a[0]), "r"(a[1]), "r"(a[2]), "r"(a[3]),
                   "r"(b[0]), "r"(b[1]));
}

__device__ __forceinline__ unsigned s2u(const void* p) {
    return (unsigned)__cvta_generic_to_shared(p);
}
__device__ __forceinline__ void cpa16(unsigned dst, const void* src) {
    asm volatile("cp.async.cg.shared.global [%0], [%1], 16;" :: "r"(dst), "l"(src));
}
__device__ __forceinline__ void cpa_commit() {
    asm volatile("cp.async.commit_group;" ::: "memory");
}
template<int N> __device__ __forceinline__ void cpa_wait() {
    asm volatile("cp.async.wait_group %0;" :: "n"(N) : "memory");
}

// copy 128x64-float tile (row stride 64 in gmem) to smem (row stride 68)
__device__ __forceinline__ void cp_tile(float* dstbase, const float* src, int tid) {
#pragma unroll
    for (int j = 0; j < 8; j++) {
        const int i = tid + 256 * j;
        const int r = i >> 4, c = (i & 15) << 2;
        cpa16(s2u(dstbase + r * 68 + c), src + r * 64 + c);
    }
}

// ---------------- mask dtype detection + canonicalization ----------------
__global__ void k_mask(const unsigned int* __restrict__ raw)
{
    __shared__ int flags[4];
    __shared__ int mode;
    const int tid = threadIdx.x;
    if (tid < 4) flags[tid] = 0;
    __syncthreads();
    unsigned int w = raw[tid];
    if (w > 1u) flags[0] = 1;
    if (w == 1u) flags[1] = 1;
    if (w != 0u && w != 0x3F800000u) flags[2] = 1;
    if (w == 0x3F800000u) flags[3] = 1;
    __syncthreads();
    if (tid == 0) {
        if (!flags[0] && flags[1])      mode = 0;
        else if (!flags[2] && flags[3]) mode = 1;
        else                            mode = 2;
    }
    __syncthreads();
    const int md = mode;
    for (int i = tid; i < 4096; i += 1024) {
        unsigned char v;
        if (md == 0)      v = (unsigned char)(((const int*)raw)[i] != 0);
        else if (md == 1) v = (unsigned char)(((const float*)raw)[i] != 0.0f);
        else              v = (unsigned char)(((const unsigned char*)raw)[i] != 0);
        g_mask[i] = v;
    }
}

// ============ GEMM core: C = A @ W^T + bias, M=4096,N=1024,K=1024 ========
// 128x128 tile, BK=16, ping-pong smem, register prefetch. 8 warps 2x4.
// smem: 2 stages x (As[128][20] + Ws[128][20]) = 10240 floats.
extern __shared__ float smem_dyn[];

template<int ROUND_SCATTER>   // 1: round to tf32 + scatter [b,h,s,d]; 0: linear raw
__device__ __forceinline__ void gemm_body(
    const float* __restrict__ A, const float* __restrict__ W,
    const float* __restrict__ bias, float* __restrict__ tgt)
{
    const int tid = threadIdx.x;
    const int bm = blockIdx.y * 128;
    const int bn = blockIdx.x * 128;
    const int w = tid >> 5, lane = tid & 31;
    const int g = lane >> 2, t = lane & 3;
    const int wm = (w >> 2) * 64, wn = (w & 3) * 32;
    const int lr = tid >> 1, lk = (tid & 1) * 8;
    const float* Ap = A + (size_t)(bm + lr) * 1024 + lk;
    const float* Wp = W + (size_t)(bn + lr) * 1024 + lk;

    float acc[4][4][4];
#pragma unroll
    for (int mt = 0; mt < 4; mt++)
#pragma unroll
        for (int nt = 0; nt < 4; nt++)
#pragma unroll
            for (int i = 0; i < 4; i++) acc[mt][nt][i] = 0.0f;

    float4 ra0, ra1, rw0, rw1;
    // prologue: chunk 0
    ra0 = *(const float4*)(Ap);     ra1 = *(const float4*)(Ap + 4);
    rw0 = *(const float4*)(Wp);     rw1 = *(const float4*)(Wp + 4);
    {
        float* pa = smem_dyn + lr * 20 + lk;
        float* pw = smem_dyn + 5120 + lr * 20 + lk;
        float4 ta = make_float4(t32(ra0.x), t32(ra0.y), t32(ra0.z), t32(ra0.w));
        float4 tb = make_float4(t32(ra1.x), t32(ra1.y), t32(ra1.z), t32(ra1.w));
        *(float4*)pa = ta; *(float4*)(pa + 4) = tb;
        ta = make_float4(t32(rw0.x), t32(rw0.y), t32(rw0.z), t32(rw0.w));
        tb = make_float4(t32(rw1.x), t32(rw1.y), t32(rw1.z), t32(rw1.w));
        *(float4*)pw = ta; *(float4*)(pw + 4) = tb;
    }
    __syncthreads();

    for (int kc = 0; kc < 64; kc++) {
        const int s = kc & 1;
        if (kc < 63) {
            const int off = (kc + 1) * 16;
            ra0 = *(const float4*)(Ap + off);     ra1 = *(const float4*)(Ap + off + 4);
            rw0 = *(const float4*)(Wp + off);     rw1 = *(const float4*)(Wp + off + 4);
        }
        const float* As = smem_dyn + s * 2560;
        const float* Ws = smem_dyn + 5120 + s * 2560;
#pragma unroll
        for (int kk = 0; kk < 2; kk++) {
            unsigned af[4][4], bf[4][2];
#pragma unroll
            for (int mt = 0; mt < 4; mt++) {
                const float* p = As + (wm + mt * 16 + g) * 20 + kk * 8 + t;
                af[mt][0] = __float_as_uint(p[0]);
                af[mt][1] = __float_as_uint(p[8 * 20]);
                af[mt][2] = __float_as_uint(p[4]);
                af[mt][3] = __float_as_uint(p[8 * 20 + 4]);
            }
#pragma unroll
            for (int nt = 0; nt < 4; nt++) {
                const float* p = Ws + (wn + nt * 8 + g) * 20 + kk * 8 + t;
                bf[nt][0] = __float_as_uint(p[0]);
                bf[nt][1] = __float_as_uint(p[4]);
            }
#pragma unroll
            for (int mt = 0; mt < 4; mt++)
#pragma unroll
                for (int nt = 0; nt < 4; nt++)
                    mma8(acc[mt][nt], af[mt], bf[nt]);
        }
        if (kc < 63) {
            const int s2 = (kc + 1) & 1;
            float* pa = smem_dyn + s2 * 2560 + lr * 20 + lk;
            float* pw = smem_dyn + 5120 + s2 * 2560 + lr * 20 + lk;
            float4 ta = make_float4(t32(ra0.x), t32(ra0.y), t32(ra0.z), t32(ra0.w));
            float4 tb = make_float4(t32(ra1.x), t32(ra1.y), t32(ra1.z), t32(ra1.w));
            *(float4*)pa = ta; *(float4*)(pa + 4) = tb;
            ta = make_float4(t32(rw0.x), t32(rw0.y), t32(rw0.z), t32(rw0.w));
            tb = make_float4(t32(rw1.x), t32(rw1.y), t32(rw1.z), t32(rw1.w));
            *(float4*)pw = ta; *(float4*)(pw + 4) = tb;
        }
        __syncthreads();
    }

#pragma unroll
    for (int mt = 0; mt < 4; mt++) {
#pragma unroll
        for (int nt = 0; nt < 4; nt++) {
            const int c0 = bn + wn + nt * 8 + 2 * t;
            const float b0v = bias[c0], b1v = bias[c0 + 1];
#pragma unroll
            for (int half = 0; half < 2; half++) {
                const int m = bm + wm + mt * 16 + g + half * 8;
                float v0 = acc[mt][nt][half * 2 + 0] + b0v;
                float v1 = acc[mt][nt][half * 2 + 1] + b1v;
                if (ROUND_SCATTER) {
                    v0 = t32(v0); v1 = t32(v1);
                    const int b = m >> 11, sr = m & 2047;
                    const int h = c0 >> 6, d = c0 & 63;
                    float* dst = tgt + (((size_t)((b << 4) + h)) * 2048 + sr) * 64 + d;
                    dst[0] = v0; dst[1] = v1;
                } else {
                    float* dst = tgt + (size_t)m * 1024 + c0;
                    dst[0] = v0; dst[1] = v1;
                }
            }
        }
    }
}

__global__ __launch_bounds__(256, 2) void k_proj(
    const float* __restrict__ A0, const float* __restrict__ A1, const float* __restrict__ A2,
    const float* __restrict__ W0, const float* __restrict__ W1, const float* __restrict__ W2,
    const float* __restrict__ b0, const float* __restrict__ b1, const float* __restrict__ b2)
{
    const int z = blockIdx.z;
    const float* A = (z == 0) ? A0 : (z == 1) ? A1 : A2;
    const float* W = (z == 0) ? W0 : (z == 1) ? W1 : W2;
    const float* b = (z == 0) ? b0 : (z == 1) ? b1 : b2;
    float* tgt = (z == 0) ? g_q : (z == 1) ? g_k : g_v;
    gemm_body<1>(A, W, b, tgt);
}

__global__ __launch_bounds__(256, 2) void k_out(
    const float* __restrict__ W, const float* __restrict__ b, float* __restrict__ out)
{
    gemm_body<0>(g_ctx, W, b, out);
}

// ============ fused attention core with cp.async pipelines ===============
// smem float layout:
//  Qs 0 (8704), Ks[2] 8704/17408, Vs 26112 (8704), Ps 34816 (16896),
//  rowsum 51712, rinv 51840, runi 51968(int), hasuni 52096, Ms@52100 (2048B)
__global__ __launch_bounds__(256) void k_attn(float* __restrict__ dattn, int use_dout)
{
    float* Qs = smem_dyn;
    float* Vs = smem_dyn + 26112;
    float* Ps = smem_dyn + 34816;
    float* rowsum = smem_dyn + 51712;
    float* rinv   = smem_dyn + 51840;
    int*   runi   = (int*)(smem_dyn + 51968);
    int*   hasuniS= (int*)(smem_dyn + 52096);
    unsigned char* Ms = (unsigned char*)(smem_dyn + 52100);

    float* attn = use_dout ? dattn : g_attn;
    const int tid = threadIdx.x;
    const int bh = blockIdx.y;
    const int bb = bh >> 4, hh = bh & 15;
    const int x = blockIdx.x;          // q-tile index
    const int q0 = x * 128;
    const float* Qp = g_q + (size_t)bh * 2048 * 64;
    const float* Kp = g_k + (size_t)bh * 2048 * 64;
    const float* Vp = g_v + (size_t)bh * 2048 * 64;

    const int w = tid >> 5, lane = tid & 31;
    const int g = lane >> 2, t = lane & 3;
    const int wmS = (w >> 2) * 64, wnS = (w & 3) * 32;   // scores map 2x4
    const int wmO = (w >> 1) * 32, wnO = (w & 1) * 32;   // PV map 4x2

    // ---- init + prologue copies (one group: Qs, Ks(0), mask) ----
    if (tid < 128) rowsum[tid] = 0.0f;
    if (tid == 0) hasuniS[0] = 0;
    cp_tile(Qs, Qp + (size_t)q0 * 64, tid);
    cp_tile(smem_dyn + 8704, Kp, tid);
    if (tid < 128)
        cpa16(s2u(Ms + tid * 16), g_mask + bb * 2048 + tid * 16);
    cpa_commit();

    // ---- Pass A: rowsum of exp over causal-live chunks, K pipelined ----
    float rs[4][2];
#pragma unroll
    for (int mt = 0; mt < 4; mt++) { rs[mt][0] = 0.0f; rs[mt][1] = 0.0f; }

    for (int kc = 0; kc <= x; kc++) {
        cpa_wait<0>();
        __syncthreads();
        if (kc < x) {
            cp_tile(smem_dyn + 8704 + ((kc + 1) & 1) * 8704,
                    Kp + (size_t)(kc + 1) * 128 * 64, tid);
            cpa_commit();
        }
        const float* Kb = smem_dyn + 8704 + (kc & 1) * 8704;
        const int kc0 = kc * 128;

        float acc[4][4][4];
#pragma unroll
        for (int mt = 0; mt < 4; mt++)
#pragma unroll
            for (int nt = 0; nt < 4; nt++)
#pragma unroll
                for (int i = 0; i < 4; i++) acc[mt][nt][i] = 0.0f;
#pragma unroll
        for (int kk = 0; kk < 8; kk++) {
            unsigned af[4][4], bf[4][2];
#pragma unroll
            for (int mt = 0; mt < 4; mt++) {
                const float* p = Qs + (wmS + mt * 16 + g) * 68 + kk * 8 + t;
                af[mt][0] = __float_as_uint(p[0]);
                af[mt][1] = __float_as_uint(p[8 * 68]);
                af[mt][2] = __float_as_uint(p[4]);
                af[mt][3] = __float_as_uint(p[8 * 68 + 4]);
            }
#pragma unroll
            for (int nt = 0; nt < 4; nt++) {
                const float* p = Kb + (wnS + nt * 8 + g) * 68 + kk * 8 + t;
                bf[nt][0] = __float_as_uint(p[0]);
                bf[nt][1] = __float_as_uint(p[4]);
            }
#pragma unroll
            for (int mt = 0; mt < 4; mt++)
#pragma unroll
                for (int nt = 0; nt < 4; nt++)
                    mma8(acc[mt][nt], af[mt], bf[nt]);
        }
#pragma unroll
        for (int nt = 0; nt < 4; nt++) {
            const int c0 = kc0 + wnS + nt * 8 + 2 * t;
            const unsigned char mk0 = Ms[c0], mk1 = Ms[c0 + 1];
#pragma unroll
            for (int mt = 0; mt < 4; mt++) {
#pragma unroll
                for (int half = 0; half < 2; half++) {
                    const int rq = q0 + wmS + mt * 16 + g + half * 8;
                    const float s0 = acc[mt][nt][half*2+0] * QK_SCALE;
                    const float s1 = acc[mt][nt][half*2+1] * QK_SCALE;
                    float e0 = (!mk0 || c0 > rq)     ? 0.0f : __expf(s0);
                    float e1 = (!mk1 || c0 + 1 > rq) ? 0.0f : __expf(s1);
                    rs[mt][half] += e0 + e1;
                }
            }
        }
    }
#pragma unroll
    for (int mt = 0; mt < 4; mt++)
#pragma unroll
        for (int half = 0; half < 2; half++) {
            float v = rs[mt][half];
            v += __shfl_xor_sync(0xffffffffu, v, 1);
            v += __shfl_xor_sync(0xffffffffu, v, 2);
            if (t == 0) atomicAdd(&rowsum[wmS + mt * 16 + g + 8 * half], v);
        }
    __syncthreads();
    if (tid < 128) {
        const float s = rowsum[tid];
        if (s == 0.0f) { runi[tid] = 1; rinv[tid] = 0.0f; hasuniS[0] = 1; }
        else           { runi[tid] = 0; rinv[tid] = 1.0f / s; }
    }
    __syncthreads();
    const int hasuni = hasuniS[0];

    // ---- Pass B ----
    float oacc[2][4][4];
#pragma unroll
    for (int mt = 0; mt < 2; mt++)
#pragma unroll
        for (int nt = 0; nt < 4; nt++)
#pragma unroll
            for (int i = 0; i < 4; i++) oacc[mt][nt][i] = 0.0f;

    // prologue: Ks(0)
    cp_tile(smem_dyn + 8704, Kp, tid);
    cpa_commit();

    for (int kc = 0; kc < 16; kc++) {
        const int kc0 = kc * 128;
        const bool live = (kc <= x);

        if (!live && !hasuni) {
            const float4 z = make_float4(0.f, 0.f, 0.f, 0.f);
#pragma unroll
            for (int u = 0; u < 16; u++) {
                const int f = tid + 256 * u;
                const int r = f >> 5, c = (f & 31) * 4;
                *(float4*)(attn + ((size_t)(bh * 2048 + q0 + r)) * 2048 + kc0 + c) = z;
            }
            continue;
        }

        if (live) {
            cpa_wait<0>();            // Ks(kc) ready
            __syncthreads();          // all readers of prior Vs/Ps done
            cp_tile(Vs, Vp + (size_t)kc0 * 64, tid);
            cpa_commit();             // group A (Vs)
            if (kc + 1 <= x) {
                cp_tile(smem_dyn + 8704 + ((kc + 1) & 1) * 8704,
                        Kp + (size_t)(kc + 1) * 128 * 64, tid);
            }
            cpa_commit();             // group B — ALWAYS committed (possibly empty)
                                      // so wait<1> below reliably drains group A.
            const float* Kb = smem_dyn + 8704 + (kc & 1) * 8704;

            float acc[4][4][4];
#pragma unroll
            for (int mt = 0; mt < 4; mt++)
#pragma unroll
                for (int nt = 0; nt < 4; nt++)
#pragma unroll
                    for (int i = 0; i < 4; i++) acc[mt][nt][i] = 0.0f;
#pragma unroll
            for (int kk = 0; kk < 8; kk++) {
                unsigned af[4][4], bf[4][2];
#pragma unroll
                for (int mt = 0; mt < 4; mt++) {
                    const float* p = Qs + (wmS + mt * 16 + g) * 68 + kk * 8 + t;
                    af[mt][0] = __float_as_uint(p[0]);
                    af[mt][1] = __float_as_uint(p[8 * 68]);
                    af[mt][2] = __float_as_uint(p[4]);
                    af[mt][3] = __float_as_uint(p[8 * 68 + 4]);
                }
#pragma unroll
                for (int nt = 0; nt < 4; nt++) {
                    const float* p = Kb + (wnS + nt * 8 + g) * 68 + kk * 8 + t;
                    bf[nt][0] = __float_as_uint(p[0]);
                    bf[nt][1] = __float_as_uint(p[4]);
                }
#pragma unroll
                for (int mt = 0; mt < 4; mt++)
#pragma unroll
                    for (int nt = 0; nt < 4; nt++)
                        mma8(acc[mt][nt], af[mt], bf[nt]);
            }
#pragma unroll
            for (int mt = 0; mt < 4; mt++) {
#pragma unroll
                for (int half = 0; half < 2; half++) {
                    const int rl = wmS + mt * 16 + g + 8 * half;
                    const int rq = q0 + rl;
                    const float ri = rinv[rl];
                    const int un = runi[rl];
#pragma unroll
                    for (int nt = 0; nt < 4; nt++) {
                        const int cl = wnS + nt * 8 + 2 * t;
                        const int c0 = kc0 + cl;
                        const unsigned char mk0 = Ms[c0], mk1 = Ms[c0 + 1];
                        const float s0 = acc[mt][nt][half*2+0] * QK_SCALE;
                        const float s1 = acc[mt][nt][half*2+1] * QK_SCALE;
                        float e0 = (!mk0 || c0 > rq)     ? 0.0f : __expf(s0);
                        float e1 = (!mk1 || c0 + 1 > rq) ? 0.0f : __expf(s1);
                        float p0 = un ? UNIF : e0 * ri;
                        float p1 = un ? UNIF : e1 * ri;
                        *(float2*)(Ps + rl * 132 + cl) = make_float2(p0, p1);
                    }
                }
            }
            cpa_wait<1>();            // drains group A (Vs); group B (next Ks) may pend
            __syncthreads();          // Ps + Vs visible to all
        } else {
            // dead chunk but some uniform rows exist
            __syncthreads();          // prior readers of Ps/Vs done
            cp_tile(Vs, Vp + (size_t)kc0 * 64, tid);
            cpa_commit();
#pragma unroll
            for (int u = 0; u < 16; u++) {
                const int f = tid + 256 * u;
                const int r = f >> 5, c = (f & 31) * 4;
                const float pvv = runi[r] ? UNIF : 0.0f;
                *(float4*)(Ps + r * 132 + c) = make_float4(pvv, pvv, pvv, pvv);
            }
            cpa_wait<0>();
            __syncthreads();
        }

        // write attn chunk from Ps (coalesced)
#pragma unroll
        for (int u = 0; u < 16; u++) {
            const int f = tid + 256 * u;
            const int r = f >> 5, c = (f & 31) * 4;
            float4 v = *(const float4*)(Ps + r * 132 + c);
            *(float4*)(attn + ((size_t)(bh * 2048 + q0 + r)) * 2048 + kc0 + c) = v;
        }

        // PV mma: oacc += t32(Ps) @ Vs
#pragma unroll
        for (int kk = 0; kk < 16; kk++) {
            unsigned af[2][4], bf[4][2];
#pragma unroll
            for (int mt = 0; mt < 2; mt++) {
                const float* p = Ps + (wmO + mt * 16 + g) * 132 + kk * 8 + t;
                af[mt][0] = __float_as_uint(t32(p[0]));
                af[mt][1] = __float_as_uint(t32(p[8 * 132]));
                af[mt][2] = __float_as_uint(t32(p[4]));
                af[mt][3] = __float_as_uint(t32(p[8 * 132 + 4]));
            }
#pragma unroll
            for (int nt = 0; nt < 4; nt++) {
                const float* p = Vs + (kk * 8 + t) * 68 + wnO + nt * 8 + g;
                bf[nt][0] = __float_as_uint(p[0]);
                bf[nt][1] = __float_as_uint(p[4 * 68]);
            }
#pragma unroll
            for (int mt = 0; mt < 2; mt++)
#pragma unroll
                for (int nt = 0; nt < 4; nt++)
                    mma8(oacc[mt][nt], af[mt], bf[nt]);
        }
    }

    // ---- write ctx ----
#pragma unroll
    for (int mt = 0; mt < 2; mt++) {
#pragma unroll
        for (int nt = 0; nt < 4; nt++) {
            const int d0 = wnO + nt * 8 + 2 * t;
#pragma unroll
            for (int half = 0; half < 2; half++) {
                const int rq = q0 + wmO + mt * 16 + g + half * 8;
                *(float2*)(g_ctx + ((size_t)(bb * 2048 + rq)) * 1024 + hh * 64 + d0)
                    = make_float2(oacc[mt][nt][half*2+0], oacc[mt][nt][half*2+1]);
            }
        }
    }
}

// ---------------- launch ----------------
extern "C" void kernel_launch(void* const* d_in, const int* in_sizes, int n_in,
                              void* d_out, int out_size)
{
    const float* q_in = (const float*)d_in[0];
    const float* k_in = (const float*)d_in[1];
    const float* v_in = (const float*)d_in[2];
    const void*  mask = d_in[3];
    const float* Wq = (const float*)d_in[4];  const float* bq = (const float*)d_in[5];
    const float* Wk = (const float*)d_in[6];  const float* bk = (const float*)d_in[7];
    const float* Wv = (const float*)d_in[8];  const float* bv = (const float*)d_in[9];
    const float* Wo = (const float*)d_in[10]; const float* bo = (const float*)d_in[11];
    float* out = (float*)d_out;

    const int use_dout = (out_size >= 4194304 + 134217728) ? 1 : 0;
    float* dattn = out + 4194304;

    const int SM_G = 10240 * 4;               // 40 KB
    const int SM_A = (52100 + 512) * 4;       // ~205.5 KB
    cudaFuncSetAttribute(k_proj, cudaFuncAttributeMaxDynamicSharedMemorySize, SM_G);
    cudaFuncSetAttribute(k_out,  cudaFuncAttributeMaxDynamicSharedMemorySize, SM_G);
    cudaFuncSetAttribute(k_attn, cudaFuncAttributeMaxDynamicSharedMemorySize, SM_A);

    k_mask<<<1, 1024>>>((const unsigned int*)mask);

    k_proj<<<dim3(8, 32, 3), 256, SM_G>>>(q_in, k_in, v_in, Wq, Wk, Wv, bq, bk, bv);
    k_attn<<<dim3(16, 32), 256, SM_A>>>(dattn, use_dout);
    k_out<<<dim3(8, 32), 256, SM_G>>>(Wo, bo, out);
}

// round 6
// speedup vs baseline: 3.3607x; 1.0188x over previous
#include <cuda_runtime.h>
#include <cstdint>
#include <cstddef>

// MHA forward: B=2, S=2048, D_MODEL=1024, H=16, DK=64
// Outputs: out [2,2048,1024] then attn [2,16,2048,2048] (fp32, concatenated).
// tf32 mma.sync everywhere; q/k/v pre-rounded to tf32 at projection epilogue.
// Fused attention kernel: 512 threads, cp.async double-buffered K stream.

#define QK_SCALE 0.125f
#define UNIF 0.00048828125f   // 1/2048, exact power of two

// ---------------- device scratch ----------------
__device__ __align__(256) float g_q[2 * 16 * 2048 * 64];
__device__ __align__(256) float g_k[2 * 16 * 2048 * 64];
__device__ __align__(256) float g_v[2 * 16 * 2048 * 64];
__device__ __align__(256) float g_ctx[4096 * 1024];
__device__ __align__(256) unsigned char g_mask[4096];
__device__ __align__(256) float g_attn[134217728];  // fallback

// ---------------- helpers ----------------
__device__ __forceinline__ float t32(float x) {
    unsigned u;
    asm("cvt.rna.tf32.f32 %0, %1;" : "=r"(u) : "f"(x));
    return __uint_as_float(u);
}

__device__ __forceinline__ void mma8(float c[4], const unsigned a[4], const unsigned b[2]) {
    asm volatile("mma.sync.aligned.m16n8k8.row.col.f32.tf32.tf32.f32 "
                 "{%0,%1,%2,%3},{%4,%5,%6,%7},{%8,%9},{%0,%1,%2,%3};"
                 : "+f"(c[0]), "+f"(c[1]), "+f"(c[2]), "+f"(c[3])
                 : "r"(a[0]), "r"(a[1]), "r"(a[2]), "r"(a[3]),
                   "r"(b[0]), "r"(b[1]));
}

__device__ __forceinline__ unsigned s2u(const void* p) {
    return (unsigned)__cvta_generic_to_shared(p);
}
__device__ __forceinline__ void cpa16(unsigned dst, const void* src) {
    asm volatile("cp.async.cg.shared.global [%0], [%1], 16;" :: "r"(dst), "l"(src));
}
__device__ __forceinline__ void cpa_commit() {
    asm volatile("cp.async.commit_group;" ::: "memory");
}
template<int N> __device__ __forceinline__ void cpa_wait() {
    asm volatile("cp.async.wait_group %0;" :: "n"(N) : "memory");
}

// copy 128x64-float tile (row stride 64 in gmem) to smem (row stride 68), 512 thr
__device__ __forceinline__ void cp_tile512(float* dstbase, const float* src, int tid) {
#pragma unroll
    for (int j = 0; j < 4; j++) {
        const int i = tid + 512 * j;
        const int r = i >> 4, c = (i & 15) << 2;
        cpa16(s2u(dstbase + r * 68 + c), src + r * 64 + c);
    }
}

// ---------------- mask dtype detection + canonicalization ----------------
__global__ void k_mask(const unsigned int* __restrict__ raw)
{
    __shared__ int flags[4];
    __shared__ int mode;
    const int tid = threadIdx.x;
    if (tid < 4) flags[tid] = 0;
    __syncthreads();
    unsigned int w = raw[tid];
    if (w > 1u) flags[0] = 1;
    if (w == 1u) flags[1] = 1;
    if (w != 0u && w != 0x3F800000u) flags[2] = 1;
    if (w == 0x3F800000u) flags[3] = 1;
    __syncthreads();
    if (tid == 0) {
        if (!flags[0] && flags[1])      mode = 0;
        else if (!flags[2] && flags[3]) mode = 1;
        else                            mode = 2;
    }
    __syncthreads();
    const int md = mode;
    for (int i = tid; i < 4096; i += 1024) {
        unsigned char v;
        if (md == 0)      v = (unsigned char)(((const int*)raw)[i] != 0);
        else if (md == 1) v = (unsigned char)(((const float*)raw)[i] != 0.0f);
        else              v = (unsigned char)(((const unsigned char*)raw)[i] != 0);
        g_mask[i] = v;
    }
}

// ============ GEMM core: C = A @ W^T + bias, M=4096,N=1024,K=1024 ========
extern __shared__ float smem_dyn[];

template<int ROUND_SCATTER>
__device__ __forceinline__ void gemm_body(
    const float* __restrict__ A, const float* __restrict__ W,
    const float* __restrict__ bias, float* __restrict__ tgt)
{
    const int tid = threadIdx.x;
    const int bm = blockIdx.y * 128;
    const int bn = blockIdx.x * 128;
    const int w = tid >> 5, lane = tid & 31;
    const int g = lane >> 2, t = lane & 3;
    const int wm = (w >> 2) * 64, wn = (w & 3) * 32;
    const int lr = tid >> 1, lk = (tid & 1) * 8;
    const float* Ap = A + (size_t)(bm + lr) * 1024 + lk;
    const float* Wp = W + (size_t)(bn + lr) * 1024 + lk;

    float acc[4][4][4];
#pragma unroll
    for (int mt = 0; mt < 4; mt++)
#pragma unroll
        for (int nt = 0; nt < 4; nt++)
#pragma unroll
            for (int i = 0; i < 4; i++) acc[mt][nt][i] = 0.0f;

    float4 ra0, ra1, rw0, rw1;
    ra0 = *(const float4*)(Ap);     ra1 = *(const float4*)(Ap + 4);
    rw0 = *(const float4*)(Wp);     rw1 = *(const float4*)(Wp + 4);
    {
        float* pa = smem_dyn + lr * 20 + lk;
        float* pw = smem_dyn + 5120 + lr * 20 + lk;
        float4 ta = make_float4(t32(ra0.x), t32(ra0.y), t32(ra0.z), t32(ra0.w));
        float4 tb = make_float4(t32(ra1.x), t32(ra1.y), t32(ra1.z), t32(ra1.w));
        *(float4*)pa = ta; *(float4*)(pa + 4) = tb;
        ta = make_float4(t32(rw0.x), t32(rw0.y), t32(rw0.z), t32(rw0.w));
        tb = make_float4(t32(rw1.x), t32(rw1.y), t32(rw1.z), t32(rw1.w));
        *(float4*)pw = ta; *(float4*)(pw + 4) = tb;
    }
    __syncthreads();

    for (int kc = 0; kc < 64; kc++) {
        const int s = kc & 1;
        if (kc < 63) {
            const int off = (kc + 1) * 16;
            ra0 = *(const float4*)(Ap + off);     ra1 = *(const float4*)(Ap + off + 4);
            rw0 = *(const float4*)(Wp + off);     rw1 = *(const float4*)(Wp + off + 4);
        }
        const float* As = smem_dyn + s * 2560;
        const float* Ws = smem_dyn + 5120 + s * 2560;
#pragma unroll
        for (int kk = 0; kk < 2; kk++) {
            unsigned af[4][4], bf[4][2];
#pragma unroll
            for (int mt = 0; mt < 4; mt++) {
                const float* p = As + (wm + mt * 16 + g) * 20 + kk * 8 + t;
                af[mt][0] = __float_as_uint(p[0]);
                af[mt][1] = __float_as_uint(p[8 * 20]);
                af[mt][2] = __float_as_uint(p[4]);
                af[mt][3] = __float_as_uint(p[8 * 20 + 4]);
            }
#pragma unroll
            for (int nt = 0; nt < 4; nt++) {
                const float* p = Ws + (wn + nt * 8 + g) * 20 + kk * 8 + t;
                bf[nt][0] = __float_as_uint(p[0]);
                bf[nt][1] = __float_as_uint(p[4]);
            }
#pragma unroll
            for (int mt = 0; mt < 4; mt++)
#pragma unroll
                for (int nt = 0; nt < 4; nt++)
                    mma8(acc[mt][nt], af[mt], bf[nt]);
        }
        if (kc < 63) {
            const int s2 = (kc + 1) & 1;
            float* pa = smem_dyn + s2 * 2560 + lr * 20 + lk;
            float* pw = smem_dyn + 5120 + s2 * 2560 + lr * 20 + lk;
            float4 ta = make_float4(t32(ra0.x), t32(ra0.y), t32(ra0.z), t32(ra0.w));
            float4 tb = make_float4(t32(ra1.x), t32(ra1.y), t32(ra1.z), t32(ra1.w));
            *(float4*)pa = ta; *(float4*)(pa + 4) = tb;
            ta = make_float4(t32(rw0.x), t32(rw0.y), t32(rw0.z), t32(rw0.w));
            tb = make_float4(t32(rw1.x), t32(rw1.y), t32(rw1.z), t32(rw1.w));
            *(float4*)pw = ta; *(float4*)(pw + 4) = tb;
        }
        __syncthreads();
    }

#pragma unroll
    for (int mt = 0; mt < 4; mt++) {
#pragma unroll
        for (int nt = 0; nt < 4; nt++) {
            const int c0 = bn + wn + nt * 8 + 2 * t;
            const float b0v = bias[c0], b1v = bias[c0 + 1];
#pragma unroll
            for (int half = 0; half < 2; half++) {
                const int m = bm + wm + mt * 16 + g + half * 8;
                float v0 = acc[mt][nt][half * 2 + 0] + b0v;
                float v1 = acc[mt][nt][half * 2 + 1] + b1v;
                if (ROUND_SCATTER) {
                    v0 = t32(v0); v1 = t32(v1);
                    const int b = m >> 11, sr = m & 2047;
                    const int h = c0 >> 6, d = c0 & 63;
                    float* dst = tgt + (((size_t)((b << 4) + h)) * 2048 + sr) * 64 + d;
                    dst[0] = v0; dst[1] = v1;
                } else {
                    float* dst = tgt + (size_t)m * 1024 + c0;
                    dst[0] = v0; dst[1] = v1;
                }
            }
        }
    }
}

__global__ __launch_bounds__(256, 2) void k_proj(
    const float* __restrict__ A0, const float* __restrict__ A1, const float* __restrict__ A2,
    const float* __restrict__ W0, const float* __restrict__ W1, const float* __restrict__ W2,
    const float* __restrict__ b0, const float* __restrict__ b1, const float* __restrict__ b2)
{
    const int z = blockIdx.z;
    const float* A = (z == 0) ? A0 : (z == 1) ? A1 : A2;
    const float* W = (z == 0) ? W0 : (z == 1) ? W1 : W2;
    const float* b = (z == 0) ? b0 : (z == 1) ? b1 : b2;
    float* tgt = (z == 0) ? g_q : (z == 1) ? g_k : g_v;
    gemm_body<1>(A, W, b, tgt);
}

__global__ __launch_bounds__(256, 2) void k_out(
    const float* __restrict__ W, const float* __restrict__ b, float* __restrict__ out)
{
    gemm_body<0>(g_ctx, W, b, out);
}

// ============ fused attention core, 512 threads ==========================
// smem float layout:
//  Qs 0 (8704), Ks[2] 8704/17408, Vs 26112 (8704), Ps 34816 (16896),
//  rowsum 51712, rinv 51840, runi 51968(int), hasuni 52096, Ms@52100 (2048B)
__global__ __launch_bounds__(512) void k_attn(float* __restrict__ dattn, int use_dout)
{
    float* Qs = smem_dyn;
    float* Vs = smem_dyn + 26112;
    float* Ps = smem_dyn + 34816;
    float* rowsum = smem_dyn + 51712;
    float* rinv   = smem_dyn + 51840;
    int*   runi   = (int*)(smem_dyn + 51968);
    int*   hasuniS= (int*)(smem_dyn + 52096);
    unsigned char* Ms = (unsigned char*)(smem_dyn + 52100);

    float* attn = use_dout ? dattn : g_attn;
    const int tid = threadIdx.x;
    const int bh = blockIdx.y;
    const int bb = bh >> 4, hh = bh & 15;
    const int x = blockIdx.x;          // q-tile index
    const int q0 = x * 128;
    const float* Qp = g_q + (size_t)bh * 2048 * 64;
    const float* Kp = g_k + (size_t)bh * 2048 * 64;
    const float* Vp = g_v + (size_t)bh * 2048 * 64;

    const int w = tid >> 5, lane = tid & 31;
    const int g = lane >> 2, t = lane & 3;
    const int wmS = (w >> 2) * 32, wnS = (w & 3) * 32;   // scores 4x4, tile 32x32
    const int wmO = (w >> 1) * 16, wnO = (w & 1) * 32;   // PV 8x2, tile 16x32

    // ---- init + prologue (one group: Qs, Ks(0), mask) ----
    if (tid < 128) rowsum[tid] = 0.0f;
    if (tid == 0) hasuniS[0] = 0;
    cp_tile512(Qs, Qp + (size_t)q0 * 64, tid);
    cp_tile512(smem_dyn + 8704, Kp, tid);
    if (tid < 128)
        cpa16(s2u(Ms + tid * 16), g_mask + bb * 2048 + tid * 16);
    cpa_commit();

    // ---- Pass A ----
    float rs[2][2];
    rs[0][0] = rs[0][1] = rs[1][0] = rs[1][1] = 0.0f;

    for (int kc = 0; kc <= x; kc++) {
        cpa_wait<0>();
        __syncthreads();
        if (kc < x) {
            cp_tile512(smem_dyn + 8704 + ((kc + 1) & 1) * 8704,
                       Kp + (size_t)(kc + 1) * 128 * 64, tid);
            cpa_commit();
        }
        const float* Kb = smem_dyn + 8704 + (kc & 1) * 8704;
        const int kc0 = kc * 128;

        float acc[2][4][4];
#pragma unroll
        for (int mt = 0; mt < 2; mt++)
#pragma unroll
            for (int nt = 0; nt < 4; nt++)
#pragma unroll
                for (int i = 0; i < 4; i++) acc[mt][nt][i] = 0.0f;
#pragma unroll
        for (int kk = 0; kk < 8; kk++) {
            unsigned af[2][4], bf[4][2];
#pragma unroll
            for (int mt = 0; mt < 2; mt++) {
                const float* p = Qs + (wmS + mt * 16 + g) * 68 + kk * 8 + t;
                af[mt][0] = __float_as_uint(p[0]);
                af[mt][1] = __float_as_uint(p[8 * 68]);
                af[mt][2] = __float_as_uint(p[4]);
                af[mt][3] = __float_as_uint(p[8 * 68 + 4]);
            }
#pragma unroll
            for (int nt = 0; nt < 4; nt++) {
                const float* p = Kb + (wnS + nt * 8 + g) * 68 + kk * 8 + t;
                bf[nt][0] = __float_as_uint(p[0]);
                bf[nt][1] = __float_as_uint(p[4]);
            }
#pragma unroll
            for (int mt = 0; mt < 2; mt++)
#pragma unroll
                for (int nt = 0; nt < 4; nt++)
                    mma8(acc[mt][nt], af[mt], bf[nt]);
        }
#pragma unroll
        for (int nt = 0; nt < 4; nt++) {
            const int c0 = kc0 + wnS + nt * 8 + 2 * t;
            const unsigned char mk0 = Ms[c0], mk1 = Ms[c0 + 1];
#pragma unroll
            for (int mt = 0; mt < 2; mt++) {
#pragma unroll
                for (int half = 0; half < 2; half++) {
                    const int rq = q0 + wmS + mt * 16 + g + half * 8;
                    const float s0 = acc[mt][nt][half*2+0] * QK_SCALE;
                    const float s1 = acc[mt][nt][half*2+1] * QK_SCALE;
                    float e0 = (!mk0 || c0 > rq)     ? 0.0f : __expf(s0);
                    float e1 = (!mk1 || c0 + 1 > rq) ? 0.0f : __expf(s1);
                    rs[mt][half] += e0 + e1;
                }
            }
        }
    }
#pragma unroll
    for (int mt = 0; mt < 2; mt++)
#pragma unroll
        for (int half = 0; half < 2; half++) {
            float v = rs[mt][half];
            v += __shfl_xor_sync(0xffffffffu, v, 1);
            v += __shfl_xor_sync(0xffffffffu, v, 2);
            if (t == 0) atomicAdd(&rowsum[wmS + mt * 16 + g + 8 * half], v);
        }
    __syncthreads();
    if (tid < 128) {
        const float s = rowsum[tid];
        if (s == 0.0f) { runi[tid] = 1; rinv[tid] = 0.0f; hasuniS[0] = 1; }
        else           { runi[tid] = 0; rinv[tid] = 1.0f / s; }
    }
    __syncthreads();
    const int hasuni = hasuniS[0];

    // ---- Pass B ----
    float oacc[4][4];
#pragma unroll
    for (int nt = 0; nt < 4; nt++)
#pragma unroll
        for (int i = 0; i < 4; i++) oacc[nt][i] = 0.0f;

    cp_tile512(smem_dyn + 8704, Kp, tid);
    cpa_commit();

    for (int kc = 0; kc < 16; kc++) {
        const int kc0 = kc * 128;
        const bool live = (kc <= x);

        if (!live && !hasuni) {
            const float4 z = make_float4(0.f, 0.f, 0.f, 0.f);
#pragma unroll
            for (int u = 0; u < 8; u++) {
                const int f = tid + 512 * u;
                const int r = f >> 5, c = (f & 31) * 4;
                *(float4*)(attn + ((size_t)(bh * 2048 + q0 + r)) * 2048 + kc0 + c) = z;
            }
            continue;
        }

        if (live) {
            cpa_wait<0>();            // Ks(kc) ready
            __syncthreads();          // prior readers of Vs/Ps done
            cp_tile512(Vs, Vp + (size_t)kc0 * 64, tid);
            cpa_commit();             // group A (Vs)
            if (kc + 1 <= x) {
                cp_tile512(smem_dyn + 8704 + ((kc + 1) & 1) * 8704,
                           Kp + (size_t)(kc + 1) * 128 * 64, tid);
            }
            cpa_commit();             // group B — always committed (may be empty)
            const float* Kb = smem_dyn + 8704 + (kc & 1) * 8704;

            float acc[2][4][4];
#pragma unroll
            for (int mt = 0; mt < 2; mt++)
#pragma unroll
                for (int nt = 0; nt < 4; nt++)
#pragma unroll
                    for (int i = 0; i < 4; i++) acc[mt][nt][i] = 0.0f;
#pragma unroll
            for (int kk = 0; kk < 8; kk++) {
                unsigned af[2][4], bf[4][2];
#pragma unroll
                for (int mt = 0; mt < 2; mt++) {
                    const float* p = Qs + (wmS + mt * 16 + g) * 68 + kk * 8 + t;
                    af[mt][0] = __float_as_uint(p[0]);
                    af[mt][1] = __float_as_uint(p[8 * 68]);
                    af[mt][2] = __float_as_uint(p[4]);
                    af[mt][3] = __float_as_uint(p[8 * 68 + 4]);
                }
#pragma unroll
                for (int nt = 0; nt < 4; nt++) {
                    const float* p = Kb + (wnS + nt * 8 + g) * 68 + kk * 8 + t;
                    bf[nt][0] = __float_as_uint(p[0]);
                    bf[nt][1] = __float_as_uint(p[4]);
                }
#pragma unroll
                for (int mt = 0; mt < 2; mt++)
#pragma unroll
                    for (int nt = 0; nt < 4; nt++)
                        mma8(acc[mt][nt], af[mt], bf[nt]);
            }
#pragma unroll
            for (int mt = 0; mt < 2; mt++) {
#pragma unroll
                for (int half = 0; half < 2; half++) {
                    const int rl = wmS + mt * 16 + g + 8 * half;
                    const int rq = q0 + rl;
                    const float ri = rinv[rl];
                    const int un = runi[rl];
#pragma unroll
                    for (int nt = 0; nt < 4; nt++) {
                        const int cl = wnS + nt * 8 + 2 * t;
                        const int c0 = kc0 + cl;
                        const unsigned char mk0 = Ms[c0], mk1 = Ms[c0 + 1];
                        const float s0 = acc[mt][nt][half*2+0] * QK_SCALE;
                        const float s1 = acc[mt][nt][half*2+1] * QK_SCALE;
                        float e0 = (!mk0 || c0 > rq)     ? 0.0f : __expf(s0);
                        float e1 = (!mk1 || c0 + 1 > rq) ? 0.0f : __expf(s1);
                        float p0 = un ? UNIF : e0 * ri;
                        float p1 = un ? UNIF : e1 * ri;
                        *(float2*)(Ps + rl * 132 + cl) = make_float2(p0, p1);
                    }
                }
            }
            cpa_wait<1>();            // drain group A (Vs)
            __syncthreads();          // Ps + Vs visible
        } else {
            __syncthreads();
            cp_tile512(Vs, Vp + (size_t)kc0 * 64, tid);
            cpa_commit();
#pragma unroll
            for (int u = 0; u < 8; u++) {
                const int f = tid + 512 * u;
                const int r = f >> 5, c = (f & 31) * 4;
                const float pvv = runi[r] ? UNIF : 0.0f;
                *(float4*)(Ps + r * 132 + c) = make_float4(pvv, pvv, pvv, pvv);
            }
            cpa_wait<0>();
            __syncthreads();
        }

        // write attn chunk from Ps (coalesced)
#pragma unroll
        for (int u = 0; u < 8; u++) {
            const int f = tid + 512 * u;
            const int r = f >> 5, c = (f & 31) * 4;
            float4 v = *(const float4*)(Ps + r * 132 + c);
            *(float4*)(attn + ((size_t)(bh * 2048 + q0 + r)) * 2048 + kc0 + c) = v;
        }

        // PV mma: oacc += t32(Ps) @ Vs   (warp tile 16x32)
#pragma unroll
        for (int kk = 0; kk < 16; kk++) {
            unsigned af[4], bf[4][2];
            {
                const float* p = Ps + (wmO + g) * 132 + kk * 8 + t;
                af[0] = __float_as_uint(t32(p[0]));
                af[1] = __float_as_uint(t32(p[8 * 132]));
                af[2] = __float_as_uint(t32(p[4]));
                af[3] = __float_as_uint(t32(p[8 * 132 + 4]));
            }
#pragma unroll
            for (int nt = 0; nt < 4; nt++) {
                const float* p = Vs + (kk * 8 + t) * 68 + wnO + nt * 8 + g;
                bf[nt][0] = __float_as_uint(p[0]);
                bf[nt][1] = __float_as_uint(p[4 * 68]);
            }
#pragma unroll
            for (int nt = 0; nt < 4; nt++)
                mma8(oacc[nt], af, bf[nt]);
        }
    }

    // ---- write ctx ----
#pragma unroll
    for (int nt = 0; nt < 4; nt++) {
        const int d0 = wnO + nt * 8 + 2 * t;
#pragma unroll
        for (int half = 0; half < 2; half++) {
            const int rq = q0 + wmO + g + half * 8;
            *(float2*)(g_ctx + ((size_t)(bb * 2048 + rq)) * 1024 + hh * 64 + d0)
                = make_float2(oacc[nt][half*2+0], oacc[nt][half*2+1]);
        }
    }
}

// ---------------- launch ----------------
extern "C" void kernel_launch(void* const* d_in, const int* in_sizes, int n_in,
                              void* d_out, int out_size)
{
    const float* q_in = (const float*)d_in[0];
    const float* k_in = (const float*)d_in[1];
    const float* v_in = (const float*)d_in[2];
    const void*  mask = d_in[3];
    const float* Wq = (const float*)d_in[4];  const float* bq = (const float*)d_in[5];
    const float* Wk = (const float*)d_in[6];  const float* bk = (const float*)d_in[7];
    const float* Wv = (const float*)d_in[8];  const float* bv = (const float*)d_in[9];
    const float* Wo = (const float*)d_in[10]; const float* bo = (const float*)d_in[11];
    float* out = (float*)d_out;

    const int use_dout = (out_size >= 4194304 + 134217728) ? 1 : 0;
    float* dattn = out + 4194304;

    const int SM_G = 10240 * 4;               // 40 KB
    const int SM_A = (52100 + 512) * 4;       // ~205.5 KB
    cudaFuncSetAttribute(k_proj, cudaFuncAttributeMaxDynamicSharedMemorySize, SM_G);
    cudaFuncSetAttribute(k_out,  cudaFuncAttributeMaxDynamicSharedMemorySize, SM_G);
    cudaFuncSetAttribute(k_attn, cudaFuncAttributeMaxDynamicSharedMemorySize, SM_A);

    k_mask<<<1, 1024>>>((const unsigned int*)mask);

    k_proj<<<dim3(8, 32, 3), 256, SM_G>>>(q_in, k_in, v_in, Wq, Wk, Wv, bq, bk, bv);
    k_attn<<<dim3(16, 32), 512, SM_A>>>(dattn, use_dout);
    k_out<<<dim3(8, 32), 256, SM_G>>>(Wo, bo, out);
}